// round 10
// baseline (speedup 1.0000x reference)
#include <cuda_runtime.h>
#include <cuda_fp16.h>
#include <math.h>
#include <stdint.h>

#define BATCH 256
#define TLEN  192
#define CENC  256
#define NGATE 128
#define NECK  32
#define TPAD  200
#define CPAD_MAX 320

// ---------------- scratch ----------------
__device__ float g_bufy[(size_t)BATCH * CENC * TLEN];            // conv output (B,C,T)
__device__ float g_pre [(size_t)2 * BATCH * TLEN * NGATE];       // lstm pre-gates
__device__ __half g_ax_hi[(size_t)BATCH * TPAD * CPAD_MAX];
__device__ __half g_ax_lo[(size_t)BATCH * TPAD * CPAD_MAX];
__device__ __half g_wb[(size_t)5 * CPAD_MAX * 256];              // (tap, c, co) fp16
__device__ float g_gbias[256];
__device__ float g_scale[3][1792];
__device__ int   g_len  [3][1792];
__device__ int   g_src  [3][BATCH][TLEN];
__device__ float g_lam  [3][BATCH][TLEN];
__device__ float g_mean [BATCH];
__device__ float g_istd [BATCH];

// ---------------- cp.async helpers ----------------
#define CP16(dst, src) \
    asm volatile("cp.async.cg.shared.global [%0], [%1], 16;" :: "r"(dst), "l"(src))
#define CPCOMMIT() asm volatile("cp.async.commit_group;")
#define CPWAIT1()  asm volatile("cp.async.wait_group 1;")
#define CPWAIT0()  asm volatile("cp.async.wait_group 0;")

__device__ __forceinline__ uint32_t smem_u32(const void* p) {
    uint32_t a;
    asm("{ .reg .u64 t; cvta.to.shared.u64 t, %1; cvt.u32.u64 %0, t; }" : "=r"(a) : "l"(p));
    return a;
}

// ---------------- threefry2x32 (bit-exact JAX PRNG) ----------------
__device__ __forceinline__ unsigned tf_rotl(unsigned v, int r) {
    return (v << r) | (v >> (32 - r));
}
__device__ __forceinline__ void threefry2x32(unsigned k0, unsigned k1,
                                             unsigned x0, unsigned x1,
                                             unsigned& o0, unsigned& o1) {
    unsigned ks2 = k0 ^ k1 ^ 0x1BD11BDAu;
    x0 += k0; x1 += k1;
#define TF_RND(r) { x0 += x1; x1 = tf_rotl(x1, r); x1 ^= x0; }
    TF_RND(13) TF_RND(15) TF_RND(26) TF_RND(6)
    x0 += k1;  x1 += ks2 + 1u;
    TF_RND(17) TF_RND(29) TF_RND(16) TF_RND(24)
    x0 += ks2; x1 += k0 + 2u;
    TF_RND(13) TF_RND(15) TF_RND(26) TF_RND(6)
    x0 += k0;  x1 += k1 + 3u;
    TF_RND(17) TF_RND(29) TF_RND(16) TF_RND(24)
    x0 += k1;  x1 += ks2 + 4u;
    TF_RND(13) TF_RND(15) TF_RND(26) TF_RND(6)
#undef TF_RND
    o0 = x0 + ks2;
    o1 = x1 + k0 + 5u;
}
__device__ __forceinline__ unsigned tf_bits32(unsigned ka, unsigned kb, unsigned i) {
    unsigned o0, o1;
    threefry2x32(ka, kb, 0u, i, o0, o1);
    return o0 ^ o1;
}

__global__ void rng_bits_kernel() {
    int id = blockIdx.x * blockDim.x + threadIdx.x;
    if (id >= 3 * 1792) return;
    int l = id / 1792, m = id % 1792;
    unsigned ka, kb;
    threefry2x32(0u, 42u, 0u, (unsigned)l, ka, kb);
    unsigned k1a, k1b, k2a, k2b;
    threefry2x32(ka, kb, 0u, 0u, k1a, k1b);
    threefry2x32(ka, kb, 0u, 1u, k2a, k2b);
    unsigned ub = tf_bits32(k1a, k1b, (unsigned)m);
    float u = __uint_as_float((ub >> 9) | 0x3f800000u) - 1.0f;
    g_scale[l][m] = fmaxf(0.5f, u + 0.5f);
    unsigned ha, hb_, la, lb_;
    threefry2x32(k2a, k2b, 0u, 0u, ha, hb_);
    threefry2x32(k2a, k2b, 0u, 1u, la, lb_);
    unsigned hbits = tf_bits32(ha, hb_, (unsigned)m);
    unsigned lbits = tf_bits32(la, lb_, (unsigned)m);
    unsigned off = ((hbits % 13u) * 9u + (lbits % 13u)) % 13u;
    g_len[l][m] = 19 + (int)off;
}

__global__ void rng_scan_kernel() {
    int id = blockIdx.x * blockDim.x + threadIdx.x;
    if (id >= 3 * BATCH) return;
    int l = id / BATCH, b = id % BATCH;
    int cnt = 0, off = 0;
    for (int s = 0; s < 7; s++) {
        int m = b * 7 + s;
        float scale = g_scale[l][m];
        int   L     = g_len[l][m];
        float Lm1   = (float)(L - 1);
        float offf  = (float)off;
        for (int j = 0; j < 64; j++) {
            float is = (float)j / scale;
            float fl = floorf(is);
            if (fl < Lm1 && (fl + offf) < 191.0f) {
                if (cnt < TLEN) {
                    g_src[l][b][cnt] = (int)(fl + offf);
                    g_lam[l][b][cnt] = is - fl;
                }
                cnt++;
            }
        }
        off += L;
    }
    for (int t = cnt; t < TLEN; t++) g_src[l][b][t] = -1;
}

// ---------------- prep_x (layer 0 only): fp32 (B,Csrc,192) -> fp16 hi/lo (B,200,Cpad) ----------------
__global__ __launch_bounds__(256)
void prep_x_kernel(const float* __restrict__ src, int Csrc, int Cpad,
                   __half* __restrict__ dhi, __half* __restrict__ dlo) {
    __shared__ float s[32][65];
    int c0 = blockIdx.x * 32;
    int t0 = blockIdx.y * 64;
    int b  = blockIdx.z;
    int tid = threadIdx.x;
    for (int i = tid; i < 32 * 64; i += 256) {
        int ci = i >> 6, tt = i & 63;
        int tsrc = t0 + tt - 2;
        float v = 0.f;
        int c = c0 + ci;
        if (c < Csrc && tsrc >= 0 && tsrc < TLEN)
            v = src[((size_t)b * Csrc + c) * TLEN + tsrc];
        s[ci][tt] = v;
    }
    __syncthreads();
    for (int i = tid; i < 64 * 32; i += 256) {
        int tdl = i >> 5, cl = i & 31;
        int td = t0 + tdl;
        if (td < TPAD) {
            float f = s[cl][tdl];
            __half hi = __float2half_rn(f);
            float lo = f - __half2float(hi);
            size_t o = ((size_t)b * TPAD + td) * Cpad + c0 + cl;
            dhi[o] = hi;
            dlo[o] = __float2half_rn(lo);
        }
    }
}

// ---------------- prep_w: fp32 (taps,Csrc,256) -> fp16 (taps,Cpad,256) ----------------
__global__ __launch_bounds__(256)
void prep_w_kernel(const float* __restrict__ w, int taps, int Csrc, int Cpad) {
    int n = gridDim.x * blockDim.x;
    int total = taps * Cpad * 256;
    for (int i = blockIdx.x * blockDim.x + threadIdx.x; i < total; i += n) {
        int tap = i / (Cpad * 256);
        int rem = i % (Cpad * 256);
        int c = rem / 256, co = rem % 256;
        float v = (c < Csrc) ? w[((size_t)tap * Csrc + c) * 256 + co] : 0.f;
        g_wb[i] = __float2half_rn(v);
    }
}

// ---------------- prep_gw: gates weight (1,256,256) + bias ----------------
__global__ __launch_bounds__(256)
void prep_gw_kernel(const float* __restrict__ kf, const float* __restrict__ bf,
                    const float* __restrict__ kb, const float* __restrict__ bb) {
    int i = blockIdx.x * blockDim.x + threadIdx.x;
    if (i < 256 * 256) {
        int c = i / 256, nn = i % 256;
        float v = (nn < 128) ? kf[(size_t)c * 128 + nn] : kb[(size_t)c * 128 + (nn - 128)];
        g_wb[i] = __float2half_rn(v);
        if (i < 256) g_gbias[i] = (i < 128) ? bf[i] : bb[i - 128];
    }
}

// ---------------- legacy-HMMA GEMM: full-M (192 rows) CTAs, W staged once ----------------
// Buffer layout per stage: W[TAPS][32][136h] | Ahi[200][40h] | Alo[200][40h]
#define A_SZ 16000   // 200 rows x 80 B

template <int TAPS>
__global__ __launch_bounds__(256, 1)
void mma_kernel(const __half* __restrict__ Ahi, const __half* __restrict__ Alo,
                const __half* __restrict__ Wgt,
                const float* __restrict__ bias, float* __restrict__ out,
                int Cpad, int tap_offset, int mode) {
    constexpr int W_SZ  = TAPS * 32 * 272;
    constexpr int BUFSZ = W_SZ + 2 * A_SZ;

    extern __shared__ char dsm[];
    const uint32_t sb = smem_u32(dsm);

    const int bn = blockIdx.x;      // n half (128 wide)
    const int bb = blockIdx.y;      // batch
    const int tid  = threadIdx.x;
    const int wid  = tid >> 5;
    const int lane = tid & 31;
    const int wm = wid >> 2;        // 0..1  -> rows wm*96 .. wm*96+95
    const int wn = wid & 3;         // 0..3
    const int n0 = bn * 128;

    float acc[6][4][4];
#pragma unroll
    for (int i = 0; i < 6; i++)
#pragma unroll
        for (int j = 0; j < 4; j++)
#pragma unroll
            for (int k = 0; k < 4; k++) acc[i][j][k] = 0.f;

    const int kchunks = Cpad >> 5;
    const int rs = Cpad >> 3;               // uint4 per activation row

    auto stage = [&](int it) {
        uint32_t buf = sb + (uint32_t)(it & 1) * BUFSZ;
        int k0 = it * 32;
        for (int i = tid; i < TAPS * 512; i += 256) {
            int tp = i >> 9, r = (i >> 4) & 31, q = i & 15;
            const uint4* srcW = (const uint4*)(Wgt + ((size_t)tp * Cpad + k0 + r) * 256 + n0);
            CP16(buf + (uint32_t)((tp * 32 + r) * 272 + q * 16), srcW + q);
        }
        // A: rows 0..195 (196 rows x 4 uint4), both splits
        const uint4* srcH = (const uint4*)(Ahi + (size_t)bb * TPAD * Cpad + k0);
        const uint4* srcL = (const uint4*)(Alo + (size_t)bb * TPAD * Cpad + k0);
        for (int i = tid; i < 784; i += 256) {
            int r = i >> 2, q = i & 3;
            CP16(buf + W_SZ + (uint32_t)(r * 80 + q * 16), srcH + (size_t)r * rs + q);
        }
        for (int i = tid; i < 784; i += 256) {
            int r = i >> 2, q = i & 3;
            CP16(buf + W_SZ + A_SZ + (uint32_t)(r * 80 + q * 16), srcL + (size_t)r * rs + q);
        }
    };

    stage(0);
    CPCOMMIT();

    for (int it = 0; it < kchunks; it++) {
        if (it + 1 < kchunks) {
            stage(it + 1);
            CPCOMMIT();
            CPWAIT1();
        } else {
            CPWAIT0();
        }
        __syncthreads();

        uint32_t buf  = sb + (uint32_t)(it & 1) * BUFSZ;
        uint32_t sahi = buf + W_SZ;
        uint32_t salo = sahi + A_SZ;

#pragma unroll
        for (int tp = 0; tp < TAPS; tp++) {
            int cshift = tap_offset + tp;
#pragma unroll
            for (int kstep = 0; kstep < 2; kstep++) {
                // B fragments: 4 n-subtiles, loaded once, reused across 6 m-subtiles
                unsigned bfr[4][2];
#pragma unroll
                for (int np = 0; np < 2; np++) {
                    int row = kstep * 16 + (lane & 15);
                    int col = wn * 32 + np * 16 + ((lane >= 16) ? 8 : 0);
                    uint32_t addr = buf + (uint32_t)((tp * 32 + row) * 272 + col * 2);
                    unsigned r0, r1, r2, r3;
                    asm volatile("ldmatrix.sync.aligned.m8n8.x4.trans.shared.b16 {%0,%1,%2,%3}, [%4];"
                                 : "=r"(r0), "=r"(r1), "=r"(r2), "=r"(r3)
                                 : "r"(addr));
                    bfr[np * 2 + 0][0] = r0; bfr[np * 2 + 0][1] = r1;
                    bfr[np * 2 + 1][0] = r2; bfr[np * 2 + 1][1] = r3;
                }
#pragma unroll
                for (int mt = 0; mt < 6; mt++) {
                    int row = wm * 96 + mt * 16 + cshift + (lane & 15);
                    int col = kstep * 16 + ((lane >> 4) * 8);
                    unsigned ah[4], al[4];
                    uint32_t adr_h = sahi + (uint32_t)(row * 80 + col * 2);
                    uint32_t adr_l = salo + (uint32_t)(row * 80 + col * 2);
                    asm volatile("ldmatrix.sync.aligned.m8n8.x4.shared.b16 {%0,%1,%2,%3}, [%4];"
                                 : "=r"(ah[0]), "=r"(ah[1]), "=r"(ah[2]), "=r"(ah[3])
                                 : "r"(adr_h));
                    asm volatile("ldmatrix.sync.aligned.m8n8.x4.shared.b16 {%0,%1,%2,%3}, [%4];"
                                 : "=r"(al[0]), "=r"(al[1]), "=r"(al[2]), "=r"(al[3])
                                 : "r"(adr_l));
#pragma unroll
                    for (int nt = 0; nt < 4; nt++) {
                        asm volatile(
                            "mma.sync.aligned.m16n8k16.row.col.f32.f16.f16.f32 "
                            "{%0,%1,%2,%3},{%4,%5,%6,%7},{%8,%9},{%0,%1,%2,%3};"
                            : "+f"(acc[mt][nt][0]), "+f"(acc[mt][nt][1]),
                              "+f"(acc[mt][nt][2]), "+f"(acc[mt][nt][3])
                            : "r"(ah[0]), "r"(ah[1]), "r"(ah[2]), "r"(ah[3]),
                              "r"(bfr[nt][0]), "r"(bfr[nt][1]));
                        asm volatile(
                            "mma.sync.aligned.m16n8k16.row.col.f32.f16.f16.f32 "
                            "{%0,%1,%2,%3},{%4,%5,%6,%7},{%8,%9},{%0,%1,%2,%3};"
                            : "+f"(acc[mt][nt][0]), "+f"(acc[mt][nt][1]),
                              "+f"(acc[mt][nt][2]), "+f"(acc[mt][nt][3])
                            : "r"(al[0]), "r"(al[1]), "r"(al[2]), "r"(al[3]),
                              "r"(bfr[nt][0]), "r"(bfr[nt][1]));
                    }
                }
            }
        }
        __syncthreads();
    }

    // epilogue
    int gid = lane >> 2, tig = lane & 3;
#pragma unroll
    for (int mt = 0; mt < 6; mt++) {
#pragma unroll
        for (int nt = 0; nt < 4; nt++) {
            int t  = wm * 96 + mt * 16 + gid;
            int co = n0 + wn * 32 + nt * 8 + tig * 2;
            float bv0 = bias[co], bv1 = bias[co + 1];
            if (mode == 0) {
                float* yp0 = out + ((size_t)bb * 256 + co) * TLEN;
                float* yp1 = yp0 + TLEN;
                yp0[t]     = acc[mt][nt][0] + bv0;
                yp1[t]     = acc[mt][nt][1] + bv1;
                yp0[t + 8] = acc[mt][nt][2] + bv0;
                yp1[t + 8] = acc[mt][nt][3] + bv1;
            } else {
                int dir0 = co >> 7, g0 = co & 127;
                int dir1 = (co + 1) >> 7, g1 = (co + 1) & 127;
                size_t r0 = ((size_t)(dir0 * BATCH + bb) * TLEN + t) * NGATE + g0;
                size_t r1 = ((size_t)(dir1 * BATCH + bb) * TLEN + t) * NGATE + g1;
                out[r0] = acc[mt][nt][0] + bv0;
                out[r1] = acc[mt][nt][1] + bv1;
                size_t r2 = ((size_t)(dir0 * BATCH + bb) * TLEN + t + 8) * NGATE + g0;
                size_t r3 = ((size_t)(dir1 * BATCH + bb) * TLEN + t + 8) * NGATE + g1;
                out[r2] = acc[mt][nt][2] + bv0;
                out[r3] = acc[mt][nt][3] + bv1;
            }
        }
    }
}

// ---------------- per-sample mean/istd over (C,T), fp32 ----------------
__global__ __launch_bounds__(256)
void stats_kernel(const float* __restrict__ y) {
    int b = blockIdx.x;
    const float4* p = (const float4*)(y + (size_t)b * CENC * TLEN);
    float s0 = 0.f, s1 = 0.f, q0 = 0.f, q1 = 0.f;
    for (int i = threadIdx.x; i < CENC * TLEN / 4; i += 256) {
        float4 v = p[i];
        s0 += v.x + v.y;
        s1 += v.z + v.w;
        q0 = fmaf(v.x, v.x, fmaf(v.y, v.y, q0));
        q1 = fmaf(v.z, v.z, fmaf(v.w, v.w, q1));
    }
    float s = s0 + s1, q = q0 + q1;
    __shared__ float sh[256], sh2[256];
    sh[threadIdx.x] = s; sh2[threadIdx.x] = q;
    __syncthreads();
    for (int k = 128; k > 0; k >>= 1) {
        if (threadIdx.x < k) { sh[threadIdx.x] += sh[threadIdx.x + k]; sh2[threadIdx.x] += sh2[threadIdx.x + k]; }
        __syncthreads();
    }
    if (threadIdx.x == 0) {
        float mm = sh[0] / (float)(CENC * TLEN);
        float var = sh2[0] / (float)(CENC * TLEN) - mm * mm;
        g_mean[b] = mm;
        g_istd[b] = rsqrtf(var + 1e-5f);
    }
}

// ---------------- fused GN + ReLU + interp gather + fp16 hi/lo transpose ----------------
__global__ __launch_bounds__(256)
void gather_fuse_kernel(const float* __restrict__ y,
                        __half* __restrict__ dhi, __half* __restrict__ dlo,
                        const float* __restrict__ gamma, const float* __restrict__ beta,
                        int layer) {
    __shared__ float s[TLEN][33];
    int b = blockIdx.x, cz = blockIdx.y;
    int c0 = cz * 32;
    float mean = g_mean[b], istd = g_istd[b];
    int tid = threadIdx.x;

    for (int i = tid; i < 32 * TLEN; i += 256) {
        int ci = i / TLEN;
        int t = i % TLEN;
        int src = g_src[layer][b][t];
        float v = 0.f;
        if (src >= 0) {
            float lam = g_lam[layer][b][t];
            const float* yr = y + ((size_t)b * CENC + c0 + ci) * TLEN;
            float r0 = fmaxf((yr[src]     - mean) * istd * gamma[src]     + beta[src],     0.f);
            float r1 = fmaxf((yr[src + 1] - mean) * istd * gamma[src + 1] + beta[src + 1], 0.f);
            v = (1.f - lam) * r0 + lam * r1;
        }
        s[t][ci] = v;
    }
    __syncthreads();

    for (int i = tid; i < TLEN * 32; i += 256) {
        int t = i >> 5, ci = i & 31;
        float f = s[t][ci];
        __half hi = __float2half_rn(f);
        float lo = f - __half2float(hi);
        size_t o = ((size_t)b * TPAD + t + 2) * CENC + c0 + ci;
        dhi[o] = hi;
        dlo[o] = __float2half_rn(lo);
    }
    if (tid < 256) {
        const int padrows[8] = {0, 1, 194, 195, 196, 197, 198, 199};
        int pr = padrows[tid >> 5], ci = tid & 31;
        size_t o = ((size_t)b * TPAD + pr) * CENC + c0 + ci;
        dhi[o] = __float2half_rn(0.f);
        dlo[o] = __float2half_rn(0.f);
    }
}

// ---------------- LSTM recurrence ----------------
__device__ __forceinline__ float sigm(float x) { return 1.f / (1.f + expf(-x)); }

__global__ __launch_bounds__(256)
void lstm_kernel(const float* __restrict__ pre,
                 const float* __restrict__ rf, const float* __restrict__ rb,
                 float* __restrict__ out) {
    __shared__ __align__(16) float Rs[32][128];
    int dir = blockIdx.y;
    const float* R = dir ? rb : rf;
    for (int i = threadIdx.x; i < 32 * 128; i += 256) Rs[i >> 7][i & 127] = R[i];
    __syncthreads();

    int warp = threadIdx.x >> 5, lane = threadIdx.x & 31;
    int b = blockIdx.x * 8 + warp;
    float h = 0.f, c = 0.f;
    const float* preb = pre + (((size_t)dir * BATCH + b) * TLEN) * NGATE;

    for (int s = 0; s < TLEN; s++) {
        int t = dir ? (TLEN - 1 - s) : s;
        const float* p = preb + (size_t)t * NGATE;
        float zi = p[lane], zf = p[32 + lane], zg = p[64 + lane], zo = p[96 + lane];
#pragma unroll
        for (int j = 0; j < 32; j++) {
            float hj = __shfl_sync(0xffffffffu, h, j);
            zi += hj * Rs[j][lane];
            zf += hj * Rs[j][32 + lane];
            zg += hj * Rs[j][64 + lane];
            zo += hj * Rs[j][96 + lane];
        }
        c = sigm(zf) * c + sigm(zi) * tanhf(zg);
        h = sigm(zo) * tanhf(c);
        out[((size_t)b * TLEN + t) * 64 + dir * 32 + lane] = h;
    }
}

// ---------------- launch ----------------
extern "C" void kernel_launch(void* const* d_in, const int* in_sizes, int n_in,
                              void* d_out, int out_size) {
    const float* x   = (const float*)d_in[0];
    const float* w0  = (const float*)d_in[1];
    const float* b0  = (const float*)d_in[2];
    const float* w1  = (const float*)d_in[3];
    const float* b1  = (const float*)d_in[4];
    const float* w2  = (const float*)d_in[5];
    const float* b2  = (const float*)d_in[6];
    const float* g0  = (const float*)d_in[7];
    const float* be0 = (const float*)d_in[8];
    const float* g1  = (const float*)d_in[9];
    const float* be1 = (const float*)d_in[10];
    const float* g2  = (const float*)d_in[11];
    const float* be2 = (const float*)d_in[12];
    const float* kf  = (const float*)d_in[13];
    const float* rf  = (const float*)d_in[14];
    const float* bf  = (const float*)d_in[15];
    const float* kb  = (const float*)d_in[16];
    const float* rb  = (const float*)d_in[17];
    const float* bb  = (const float*)d_in[18];

    float *bufy, *pre, *gbias;
    __half *axh, *axl, *wb;
    cudaGetSymbolAddress((void**)&bufy, g_bufy);
    cudaGetSymbolAddress((void**)&pre,  g_pre);
    cudaGetSymbolAddress((void**)&gbias, g_gbias);
    cudaGetSymbolAddress((void**)&axh, g_ax_hi);
    cudaGetSymbolAddress((void**)&axl, g_ax_lo);
    cudaGetSymbolAddress((void**)&wb,  g_wb);

    const int SMEM5 = 2 * (5 * 32 * 272 + 2 * A_SZ);   // 151040
    const int SMEM1 = 2 * (1 * 32 * 272 + 2 * A_SZ);   // 81408
    cudaFuncSetAttribute(mma_kernel<5>, cudaFuncAttributeMaxDynamicSharedMemorySize, SMEM5);
    cudaFuncSetAttribute(mma_kernel<1>, cudaFuncAttributeMaxDynamicSharedMemorySize, SMEM1);

    rng_bits_kernel<<<21, 256>>>();
    rng_scan_kernel<<<3, 256>>>();

    dim3 gmma(2, BATCH);
    dim3 ggath(BATCH, 8);

    // layer 0 (Csrc=257, Cpad=320)
    prep_w_kernel<<<320, 256>>>(w0, 5, 257, 320);
    prep_x_kernel<<<dim3(10, 4, BATCH), 256>>>(x, 257, 320, axh, axl);
    mma_kernel<5><<<gmma, 256, SMEM5>>>(axh, axl, wb, b0, bufy, 320, 0, 0);
    stats_kernel<<<BATCH, 256>>>(bufy);
    gather_fuse_kernel<<<ggath, 256>>>(bufy, axh, axl, g0, be0, 0);
    // layer 1 (Cpad=256)
    prep_w_kernel<<<256, 256>>>(w1, 5, 256, 256);
    mma_kernel<5><<<gmma, 256, SMEM5>>>(axh, axl, wb, b1, bufy, 256, 0, 0);
    stats_kernel<<<BATCH, 256>>>(bufy);
    gather_fuse_kernel<<<ggath, 256>>>(bufy, axh, axl, g1, be1, 1);
    // layer 2
    prep_w_kernel<<<256, 256>>>(w2, 5, 256, 256);
    mma_kernel<5><<<gmma, 256, SMEM5>>>(axh, axl, wb, b2, bufy, 256, 0, 0);
    stats_kernel<<<BATCH, 256>>>(bufy);
    gather_fuse_kernel<<<ggath, 256>>>(bufy, axh, axl, g2, be2, 2);

    // gates GEMM: taps=1 at offset 2 (time t), mode 1
    prep_gw_kernel<<<256, 256>>>(kf, bf, kb, bb);
    mma_kernel<1><<<gmma, 256, SMEM1>>>(axh, axl, wb, gbias, pre, 256, 2, 1);

    lstm_kernel<<<dim3(32, 2), 256>>>(pre, rf, rb, (float*)d_out);
}

// round 11
// speedup vs baseline: 1.0747x; 1.0747x over previous
#include <cuda_runtime.h>
#include <cuda_fp16.h>
#include <math.h>
#include <stdint.h>

#define BATCH 256
#define TLEN  192
#define CENC  256
#define NGATE 128
#define NECK  32
#define TPAD  200
#define CPAD_MAX 320

// ---------------- scratch ----------------
__device__ float g_bufy[(size_t)BATCH * CENC * TLEN];            // conv output (B,C,T)
__device__ float g_pre [(size_t)2 * BATCH * TLEN * NGATE];       // lstm pre-gates
__device__ __half g_ax_hi[(size_t)BATCH * TPAD * CPAD_MAX];
__device__ __half g_ax_lo[(size_t)BATCH * TPAD * CPAD_MAX];
__device__ __half g_wb0[(size_t)5 * 320 * 256];                  // layer0 weights (tap,c,co)
__device__ __half g_wb1[(size_t)5 * 256 * 256];
__device__ __half g_wb2[(size_t)5 * 256 * 256];
__device__ __half g_wbg[(size_t)256 * 256];                      // gates weights
__device__ float g_gbias[256];
__device__ float g_psum [BATCH][6];                              // per-tile partial sums
__device__ float g_psum2[BATCH][6];
__device__ float g_scale[3][1792];
__device__ int   g_len  [3][1792];
__device__ int   g_src  [3][BATCH][TLEN];
__device__ float g_lam  [3][BATCH][TLEN];

// ---------------- cp.async helpers ----------------
#define CP16(dst, src) \
    asm volatile("cp.async.cg.shared.global [%0], [%1], 16;" :: "r"(dst), "l"(src))
#define CPCOMMIT() asm volatile("cp.async.commit_group;")
#define CPWAIT1()  asm volatile("cp.async.wait_group 1;")
#define CPWAIT0()  asm volatile("cp.async.wait_group 0;")

__device__ __forceinline__ uint32_t smem_u32(const void* p) {
    uint32_t a;
    asm("{ .reg .u64 t; cvta.to.shared.u64 t, %1; cvt.u32.u64 %0, t; }" : "=r"(a) : "l"(p));
    return a;
}

// ---------------- threefry2x32 (bit-exact JAX PRNG) ----------------
__device__ __forceinline__ unsigned tf_rotl(unsigned v, int r) {
    return (v << r) | (v >> (32 - r));
}
__device__ __forceinline__ void threefry2x32(unsigned k0, unsigned k1,
                                             unsigned x0, unsigned x1,
                                             unsigned& o0, unsigned& o1) {
    unsigned ks2 = k0 ^ k1 ^ 0x1BD11BDAu;
    x0 += k0; x1 += k1;
#define TF_RND(r) { x0 += x1; x1 = tf_rotl(x1, r); x1 ^= x0; }
    TF_RND(13) TF_RND(15) TF_RND(26) TF_RND(6)
    x0 += k1;  x1 += ks2 + 1u;
    TF_RND(17) TF_RND(29) TF_RND(16) TF_RND(24)
    x0 += ks2; x1 += k0 + 2u;
    TF_RND(13) TF_RND(15) TF_RND(26) TF_RND(6)
    x0 += k0;  x1 += k1 + 3u;
    TF_RND(17) TF_RND(29) TF_RND(16) TF_RND(24)
    x0 += k1;  x1 += ks2 + 4u;
    TF_RND(13) TF_RND(15) TF_RND(26) TF_RND(6)
#undef TF_RND
    o0 = x0 + ks2;
    o1 = x1 + k0 + 5u;
}
__device__ __forceinline__ unsigned tf_bits32(unsigned ka, unsigned kb, unsigned i) {
    unsigned o0, o1;
    threefry2x32(ka, kb, 0u, i, o0, o1);
    return o0 ^ o1;
}

__global__ void rng_bits_kernel() {
    int id = blockIdx.x * blockDim.x + threadIdx.x;
    if (id >= 3 * 1792) return;
    int l = id / 1792, m = id % 1792;
    unsigned ka, kb;
    threefry2x32(0u, 42u, 0u, (unsigned)l, ka, kb);
    unsigned k1a, k1b, k2a, k2b;
    threefry2x32(ka, kb, 0u, 0u, k1a, k1b);
    threefry2x32(ka, kb, 0u, 1u, k2a, k2b);
    unsigned ub = tf_bits32(k1a, k1b, (unsigned)m);
    float u = __uint_as_float((ub >> 9) | 0x3f800000u) - 1.0f;
    g_scale[l][m] = fmaxf(0.5f, u + 0.5f);
    unsigned ha, hb_, la, lb_;
    threefry2x32(k2a, k2b, 0u, 0u, ha, hb_);
    threefry2x32(k2a, k2b, 0u, 1u, la, lb_);
    unsigned hbits = tf_bits32(ha, hb_, (unsigned)m);
    unsigned lbits = tf_bits32(la, lb_, (unsigned)m);
    unsigned off = ((hbits % 13u) * 9u + (lbits % 13u)) % 13u;
    g_len[l][m] = 19 + (int)off;
}

__global__ void rng_scan_kernel() {
    int id = blockIdx.x * blockDim.x + threadIdx.x;
    if (id >= 3 * BATCH) return;
    int l = id / BATCH, b = id % BATCH;
    int cnt = 0, off = 0;
    for (int s = 0; s < 7; s++) {
        int m = b * 7 + s;
        float scale = g_scale[l][m];
        int   L     = g_len[l][m];
        float Lm1   = (float)(L - 1);
        float offf  = (float)off;
        for (int j = 0; j < 64; j++) {
            float is = (float)j / scale;
            float fl = floorf(is);
            if (fl < Lm1 && (fl + offf) < 191.0f) {
                if (cnt < TLEN) {
                    g_src[l][b][cnt] = (int)(fl + offf);
                    g_lam[l][b][cnt] = is - fl;
                }
                cnt++;
            }
        }
        off += L;
    }
    for (int t = cnt; t < TLEN; t++) g_src[l][b][t] = -1;
}

// ---------------- prep_x (layer 0 only): fp32 (B,Csrc,192) -> fp16 hi/lo (B,200,Cpad) ----------------
__global__ __launch_bounds__(256)
void prep_x_kernel(const float* __restrict__ src, int Csrc, int Cpad,
                   __half* __restrict__ dhi, __half* __restrict__ dlo) {
    __shared__ float s[32][65];
    int c0 = blockIdx.x * 32;
    int t0 = blockIdx.y * 64;
    int b  = blockIdx.z;
    int tid = threadIdx.x;
    for (int i = tid; i < 32 * 64; i += 256) {
        int ci = i >> 6, tt = i & 63;
        int tsrc = t0 + tt - 2;
        float v = 0.f;
        int c = c0 + ci;
        if (c < Csrc && tsrc >= 0 && tsrc < TLEN)
            v = src[((size_t)b * Csrc + c) * TLEN + tsrc];
        s[ci][tt] = v;
    }
    __syncthreads();
    for (int i = tid; i < 64 * 32; i += 256) {
        int tdl = i >> 5, cl = i & 31;
        int td = t0 + tdl;
        if (td < TPAD) {
            float f = s[cl][tdl];
            __half hi = __float2half_rn(f);
            float lo = f - __half2float(hi);
            size_t o = ((size_t)b * TPAD + td) * Cpad + c0 + cl;
            dhi[o] = hi;
            dlo[o] = __float2half_rn(lo);
        }
    }
}

// ---------------- prep_w: fp32 (taps,Csrc,256) -> fp16 (taps,Cpad,256) ----------------
__global__ __launch_bounds__(256)
void prep_w_kernel(const float* __restrict__ w, __half* __restrict__ dst,
                   int taps, int Csrc, int Cpad) {
    int n = gridDim.x * blockDim.x;
    int total = taps * Cpad * 256;
    for (int i = blockIdx.x * blockDim.x + threadIdx.x; i < total; i += n) {
        int tap = i / (Cpad * 256);
        int rem = i % (Cpad * 256);
        int c = rem / 256, co = rem % 256;
        float v = (c < Csrc) ? w[((size_t)tap * Csrc + c) * 256 + co] : 0.f;
        dst[i] = __float2half_rn(v);
    }
}

// ---------------- prep_gw: gates weight (1,256,256) + bias ----------------
__global__ __launch_bounds__(256)
void prep_gw_kernel(const float* __restrict__ kf, const float* __restrict__ bf,
                    const float* __restrict__ kb, const float* __restrict__ bb) {
    int i = blockIdx.x * blockDim.x + threadIdx.x;
    if (i < 256 * 256) {
        int c = i / 256, nn = i % 256;
        float v = (nn < 128) ? kf[(size_t)c * 128 + nn] : kb[(size_t)c * 128 + (nn - 128)];
        g_wbg[i] = __float2half_rn(v);
        if (i < 256) g_gbias[i] = (i < 128) ? bf[i] : bb[i - 128];
    }
}

// ---------------- legacy-HMMA GEMM (R9 config): W staged once per k-chunk, splits fused ----------------
// Buffer layout per stage: W[TAPS][32][136h] | Ahi[68][40h] | Alo[68][40h]
#define A_SZ 5440

template <int TAPS>
__global__ __launch_bounds__(256)
void mma_kernel(const __half* __restrict__ Ahi, const __half* __restrict__ Alo,
                const __half* __restrict__ Wgt,
                const float* __restrict__ bias, float* __restrict__ out,
                int Cpad, int tap_offset, int mode) {
    constexpr int W_SZ  = TAPS * 32 * 272;
    constexpr int BUFSZ = W_SZ + 2 * A_SZ;

    extern __shared__ char dsm[];
    const uint32_t sb = smem_u32(dsm);

    const int bn = blockIdx.x;      // n tile (128 wide)
    const int bm = blockIdx.y;      // m tile (64 wide)
    const int bb = blockIdx.z;      // batch
    const int tid  = threadIdx.x;
    const int wid  = tid >> 5;
    const int lane = tid & 31;
    const int wm = wid >> 2;        // 0..1
    const int wn = wid & 3;         // 0..3
    const int t0 = bm * 64;
    const int n0 = bn * 128;

    float acc[2][4][4];
#pragma unroll
    for (int i = 0; i < 2; i++)
#pragma unroll
        for (int j = 0; j < 4; j++)
#pragma unroll
            for (int k = 0; k < 4; k++) acc[i][j][k] = 0.f;

    const int kchunks = Cpad >> 5;
    const int rs = Cpad >> 3;               // uint4 per activation row

    auto stage = [&](int it) {
        uint32_t buf = sb + (uint32_t)(it & 1) * BUFSZ;
        int k0 = it * 32;
        for (int i = tid; i < TAPS * 512; i += 256) {
            int tp = i >> 9, r = (i >> 4) & 31, q = i & 15;
            const uint4* srcW = (const uint4*)(Wgt + ((size_t)tp * Cpad + k0 + r) * 256 + n0);
            CP16(buf + (uint32_t)((tp * 32 + r) * 272 + q * 16), srcW + q);
        }
        const uint4* srcH = (const uint4*)(Ahi + ((size_t)bb * TPAD + t0) * Cpad + k0);
        const uint4* srcL = (const uint4*)(Alo + ((size_t)bb * TPAD + t0) * Cpad + k0);
        for (int i = tid; i < 272; i += 256) {
            int r = i >> 2, q = i & 3;
            CP16(buf + W_SZ + (uint32_t)(r * 80 + q * 16), srcH + (size_t)r * rs + q);
        }
        for (int i = tid; i < 272; i += 256) {
            int r = i >> 2, q = i & 3;
            CP16(buf + W_SZ + A_SZ + (uint32_t)(r * 80 + q * 16), srcL + (size_t)r * rs + q);
        }
    };

    stage(0);
    CPCOMMIT();

    for (int it = 0; it < kchunks; it++) {
        if (it + 1 < kchunks) {
            stage(it + 1);
            CPCOMMIT();
            CPWAIT1();
        } else {
            CPWAIT0();
        }
        __syncthreads();

        uint32_t buf  = sb + (uint32_t)(it & 1) * BUFSZ;
        uint32_t sahi = buf + W_SZ;
        uint32_t salo = sahi + A_SZ;

#pragma unroll
        for (int tp = 0; tp < TAPS; tp++) {
            int cshift = tap_offset + tp;
#pragma unroll
            for (int kstep = 0; kstep < 2; kstep++) {
                unsigned ah[2][4], al[2][4];
#pragma unroll
                for (int mt = 0; mt < 2; mt++) {
                    int row = wm * 32 + mt * 16 + cshift + (lane & 15);
                    int col = kstep * 16 + ((lane >> 4) * 8);
                    uint32_t adr_h = sahi + (uint32_t)(row * 80 + col * 2);
                    uint32_t adr_l = salo + (uint32_t)(row * 80 + col * 2);
                    asm volatile("ldmatrix.sync.aligned.m8n8.x4.shared.b16 {%0,%1,%2,%3}, [%4];"
                                 : "=r"(ah[mt][0]), "=r"(ah[mt][1]), "=r"(ah[mt][2]), "=r"(ah[mt][3])
                                 : "r"(adr_h));
                    asm volatile("ldmatrix.sync.aligned.m8n8.x4.shared.b16 {%0,%1,%2,%3}, [%4];"
                                 : "=r"(al[mt][0]), "=r"(al[mt][1]), "=r"(al[mt][2]), "=r"(al[mt][3])
                                 : "r"(adr_l));
                }
                unsigned bfr[4][2];
#pragma unroll
                for (int np = 0; np < 2; np++) {
                    int row = kstep * 16 + (lane & 15);
                    int col = wn * 32 + np * 16 + ((lane >= 16) ? 8 : 0);
                    uint32_t addr = buf + (uint32_t)((tp * 32 + row) * 272 + col * 2);
                    unsigned r0, r1, r2, r3;
                    asm volatile("ldmatrix.sync.aligned.m8n8.x4.trans.shared.b16 {%0,%1,%2,%3}, [%4];"
                                 : "=r"(r0), "=r"(r1), "=r"(r2), "=r"(r3)
                                 : "r"(addr));
                    bfr[np * 2 + 0][0] = r0; bfr[np * 2 + 0][1] = r1;
                    bfr[np * 2 + 1][0] = r2; bfr[np * 2 + 1][1] = r3;
                }
#pragma unroll
                for (int mt = 0; mt < 2; mt++)
#pragma unroll
                    for (int nt = 0; nt < 4; nt++) {
                        asm volatile(
                            "mma.sync.aligned.m16n8k16.row.col.f32.f16.f16.f32 "
                            "{%0,%1,%2,%3},{%4,%5,%6,%7},{%8,%9},{%0,%1,%2,%3};"
                            : "+f"(acc[mt][nt][0]), "+f"(acc[mt][nt][1]),
                              "+f"(acc[mt][nt][2]), "+f"(acc[mt][nt][3])
                            : "r"(ah[mt][0]), "r"(ah[mt][1]), "r"(ah[mt][2]), "r"(ah[mt][3]),
                              "r"(bfr[nt][0]), "r"(bfr[nt][1]));
                        asm volatile(
                            "mma.sync.aligned.m16n8k16.row.col.f32.f16.f16.f32 "
                            "{%0,%1,%2,%3},{%4,%5,%6,%7},{%8,%9},{%0,%1,%2,%3};"
                            : "+f"(acc[mt][nt][0]), "+f"(acc[mt][nt][1]),
                              "+f"(acc[mt][nt][2]), "+f"(acc[mt][nt][3])
                            : "r"(al[mt][0]), "r"(al[mt][1]), "r"(al[mt][2]), "r"(al[mt][3]),
                              "r"(bfr[nt][0]), "r"(bfr[nt][1]));
                    }
            }
        }
        __syncthreads();
    }

    // epilogue (+ fused partial GN stats in mode 0)
    int gid = lane >> 2, tig = lane & 3;
    float psum = 0.f, psum2 = 0.f;
#pragma unroll
    for (int mt = 0; mt < 2; mt++) {
#pragma unroll
        for (int nt = 0; nt < 4; nt++) {
            int t  = t0 + wm * 32 + mt * 16 + gid;
            int co = n0 + wn * 32 + nt * 8 + tig * 2;
            float bv0 = bias[co], bv1 = bias[co + 1];
            float v0 = acc[mt][nt][0] + bv0;
            float v1 = acc[mt][nt][1] + bv1;
            float v2 = acc[mt][nt][2] + bv0;
            float v3 = acc[mt][nt][3] + bv1;
            if (mode == 0) {
                float* yp0 = out + ((size_t)bb * 256 + co) * TLEN;
                float* yp1 = yp0 + TLEN;
                yp0[t]     = v0;
                yp1[t]     = v1;
                yp0[t + 8] = v2;
                yp1[t + 8] = v3;
                psum  += v0 + v1 + v2 + v3;
                psum2 = fmaf(v0, v0, fmaf(v1, v1, fmaf(v2, v2, fmaf(v3, v3, psum2))));
            } else {
                int dir0 = co >> 7, g0 = co & 127;
                int dir1 = (co + 1) >> 7, g1 = (co + 1) & 127;
                size_t r0 = ((size_t)(dir0 * BATCH + bb) * TLEN + t) * NGATE + g0;
                size_t r1 = ((size_t)(dir1 * BATCH + bb) * TLEN + t) * NGATE + g1;
                out[r0] = v0;
                out[r1] = v1;
                size_t r2 = ((size_t)(dir0 * BATCH + bb) * TLEN + t + 8) * NGATE + g0;
                size_t r3 = ((size_t)(dir1 * BATCH + bb) * TLEN + t + 8) * NGATE + g1;
                out[r2] = v2;
                out[r3] = v3;
            }
        }
    }
    if (mode == 0) {
        float* red = (float*)dsm;      // reuse staging smem (all loads done)
        __syncthreads();
        red[tid] = psum;
        red[256 + tid] = psum2;
        __syncthreads();
        for (int k = 128; k > 0; k >>= 1) {
            if (tid < k) {
                red[tid] += red[tid + k];
                red[256 + tid] += red[256 + tid + k];
            }
            __syncthreads();
        }
        if (tid == 0) {
            g_psum [bb][bm * 2 + bn] = red[0];
            g_psum2[bb][bm * 2 + bn] = red[256];
        }
    }
}

// ---------------- fused GN + ReLU + interp gather + fp16 hi/lo transpose ----------------
__global__ __launch_bounds__(256)
void gather_fuse_kernel(const float* __restrict__ y,
                        __half* __restrict__ dhi, __half* __restrict__ dlo,
                        const float* __restrict__ gamma, const float* __restrict__ beta,
                        int layer) {
    __shared__ float s[TLEN][33];
    int b = blockIdx.x, cz = blockIdx.y;
    int c0 = cz * 32;
    int tid = threadIdx.x;

    // fold the 6 tile partials -> mean/istd (fixed order, deterministic)
    float ts = 0.f, tq = 0.f;
#pragma unroll
    for (int i = 0; i < 6; i++) { ts += g_psum[b][i]; tq += g_psum2[b][i]; }
    const float inv_n = 1.0f / (float)(CENC * TLEN);
    float mean = ts * inv_n;
    float istd = rsqrtf(fmaxf(tq * inv_n - mean * mean, 0.f) + 1e-5f);

    for (int i = tid; i < 32 * TLEN; i += 256) {
        int ci = i / TLEN;
        int t = i % TLEN;
        int src = g_src[layer][b][t];
        float v = 0.f;
        if (src >= 0) {
            float lam = g_lam[layer][b][t];
            const float* yr = y + ((size_t)b * CENC + c0 + ci) * TLEN;
            float r0 = fmaxf((yr[src]     - mean) * istd * gamma[src]     + beta[src],     0.f);
            float r1 = fmaxf((yr[src + 1] - mean) * istd * gamma[src + 1] + beta[src + 1], 0.f);
            v = (1.f - lam) * r0 + lam * r1;
        }
        s[t][ci] = v;
    }
    __syncthreads();

    for (int i = tid; i < TLEN * 32; i += 256) {
        int t = i >> 5, ci = i & 31;
        float f = s[t][ci];
        __half hi = __float2half_rn(f);
        float lo = f - __half2float(hi);
        size_t o = ((size_t)b * TPAD + t + 2) * CENC + c0 + ci;
        dhi[o] = hi;
        dlo[o] = __float2half_rn(lo);
    }
    if (tid < 256) {
        const int padrows[8] = {0, 1, 194, 195, 196, 197, 198, 199};
        int pr = padrows[tid >> 5], ci = tid & 31;
        size_t o = ((size_t)b * TPAD + pr) * CENC + c0 + ci;
        dhi[o] = __float2half_rn(0.f);
        dlo[o] = __float2half_rn(0.f);
    }
}

// ---------------- LSTM recurrence ----------------
__device__ __forceinline__ float sigm(float x) { return 1.f / (1.f + expf(-x)); }

__global__ __launch_bounds__(256)
void lstm_kernel(const float* __restrict__ pre,
                 const float* __restrict__ rf, const float* __restrict__ rb,
                 float* __restrict__ out) {
    __shared__ __align__(16) float Rs[32][128];
    int dir = blockIdx.y;
    const float* R = dir ? rb : rf;
    for (int i = threadIdx.x; i < 32 * 128; i += 256) Rs[i >> 7][i & 127] = R[i];
    __syncthreads();

    int warp = threadIdx.x >> 5, lane = threadIdx.x & 31;
    int b = blockIdx.x * 8 + warp;
    float h = 0.f, c = 0.f;
    const float* preb = pre + (((size_t)dir * BATCH + b) * TLEN) * NGATE;

    for (int s = 0; s < TLEN; s++) {
        int t = dir ? (TLEN - 1 - s) : s;
        const float* p = preb + (size_t)t * NGATE;
        float zi = p[lane], zf = p[32 + lane], zg = p[64 + lane], zo = p[96 + lane];
#pragma unroll
        for (int j = 0; j < 32; j++) {
            float hj = __shfl_sync(0xffffffffu, h, j);
            zi += hj * Rs[j][lane];
            zf += hj * Rs[j][32 + lane];
            zg += hj * Rs[j][64 + lane];
            zo += hj * Rs[j][96 + lane];
        }
        c = sigm(zf) * c + sigm(zi) * tanhf(zg);
        h = sigm(zo) * tanhf(c);
        out[((size_t)b * TLEN + t) * 64 + dir * 32 + lane] = h;
    }
}

// ---------------- launch ----------------
extern "C" void kernel_launch(void* const* d_in, const int* in_sizes, int n_in,
                              void* d_out, int out_size) {
    const float* x   = (const float*)d_in[0];
    const float* w0  = (const float*)d_in[1];
    const float* b0  = (const float*)d_in[2];
    const float* w1  = (const float*)d_in[3];
    const float* b1  = (const float*)d_in[4];
    const float* w2  = (const float*)d_in[5];
    const float* b2  = (const float*)d_in[6];
    const float* g0  = (const float*)d_in[7];
    const float* be0 = (const float*)d_in[8];
    const float* g1  = (const float*)d_in[9];
    const float* be1 = (const float*)d_in[10];
    const float* g2  = (const float*)d_in[11];
    const float* be2 = (const float*)d_in[12];
    const float* kf  = (const float*)d_in[13];
    const float* rf  = (const float*)d_in[14];
    const float* bf  = (const float*)d_in[15];
    const float* kb  = (const float*)d_in[16];
    const float* rb  = (const float*)d_in[17];
    const float* bb  = (const float*)d_in[18];

    float *bufy, *pre, *gbias;
    __half *axh, *axl, *wb0, *wb1, *wb2, *wbg;
    cudaGetSymbolAddress((void**)&bufy, g_bufy);
    cudaGetSymbolAddress((void**)&pre,  g_pre);
    cudaGetSymbolAddress((void**)&gbias, g_gbias);
    cudaGetSymbolAddress((void**)&axh, g_ax_hi);
    cudaGetSymbolAddress((void**)&axl, g_ax_lo);
    cudaGetSymbolAddress((void**)&wb0, g_wb0);
    cudaGetSymbolAddress((void**)&wb1, g_wb1);
    cudaGetSymbolAddress((void**)&wb2, g_wb2);
    cudaGetSymbolAddress((void**)&wbg, g_wbg);

    const int SMEM5 = 2 * (5 * 32 * 272 + 2 * A_SZ);   // 108800
    const int SMEM1 = 2 * (1 * 32 * 272 + 2 * A_SZ);   // 39168
    cudaFuncSetAttribute(mma_kernel<5>, cudaFuncAttributeMaxDynamicSharedMemorySize, SMEM5);
    cudaFuncSetAttribute(mma_kernel<1>, cudaFuncAttributeMaxDynamicSharedMemorySize, SMEM1);

    // independent preprocessing — all up front
    rng_bits_kernel<<<21, 256>>>();
    rng_scan_kernel<<<3, 256>>>();
    prep_w_kernel<<<320, 256>>>(w0, wb0, 5, 257, 320);
    prep_w_kernel<<<256, 256>>>(w1, wb1, 5, 256, 256);
    prep_w_kernel<<<256, 256>>>(w2, wb2, 5, 256, 256);
    prep_gw_kernel<<<256, 256>>>(kf, bf, kb, bb);
    prep_x_kernel<<<dim3(10, 4, BATCH), 256>>>(x, 257, 320, axh, axl);

    dim3 gmma(2, 3, BATCH);
    dim3 ggath(BATCH, 8);

    // layer 0 (Cpad=320)
    mma_kernel<5><<<gmma, 256, SMEM5>>>(axh, axl, wb0, b0, bufy, 320, 0, 0);
    gather_fuse_kernel<<<ggath, 256>>>(bufy, axh, axl, g0, be0, 0);
    // layer 1 (Cpad=256)
    mma_kernel<5><<<gmma, 256, SMEM5>>>(axh, axl, wb1, b1, bufy, 256, 0, 0);
    gather_fuse_kernel<<<ggath, 256>>>(bufy, axh, axl, g1, be1, 1);
    // layer 2
    mma_kernel<5><<<gmma, 256, SMEM5>>>(axh, axl, wb2, b2, bufy, 256, 0, 0);
    gather_fuse_kernel<<<ggath, 256>>>(bufy, axh, axl, g2, be2, 2);

    // gates GEMM: taps=1 at offset 2 (time t), mode 1
    mma_kernel<1><<<gmma, 256, SMEM1>>>(axh, axl, wbg, gbias, pre, 256, 2, 1);

    lstm_kernel<<<dim3(32, 2), 256>>>(pre, rf, rb, (float*)d_out);
}

// round 12
// speedup vs baseline: 1.1227x; 1.0447x over previous
#include <cuda_runtime.h>
#include <cuda_fp16.h>
#include <math.h>
#include <stdint.h>

#define BATCH 256
#define TLEN  192
#define CENC  256
#define NGATE 128
#define NECK  32
#define TPAD  200
#define CPAD_MAX 288

// ---------------- scratch ----------------
__device__ float g_bufy[(size_t)BATCH * CENC * TLEN];            // conv output (B,C,T)
__device__ float g_pre [(size_t)2 * BATCH * TLEN * NGATE];       // lstm pre-gates (gate-interleaved)
__device__ __half g_ax_hi[(size_t)BATCH * TPAD * CPAD_MAX];
__device__ __half g_ax_lo[(size_t)BATCH * TPAD * CPAD_MAX];
__device__ __half g_wb0[(size_t)5 * 288 * 256];                  // layer0 weights (tap,c,co)
__device__ __half g_wb1[(size_t)5 * 256 * 256];
__device__ __half g_wb2[(size_t)5 * 256 * 256];
__device__ __half g_wbg[(size_t)256 * 256];                      // gates weights
__device__ float g_gbias[256];
__device__ float g_psum [BATCH][6];                              // per-tile partial sums
__device__ float g_psum2[BATCH][6];
__device__ float g_scale[3][1792];
__device__ int   g_len  [3][1792];
__device__ int   g_src  [3][BATCH][TLEN];
__device__ float g_lam  [3][BATCH][TLEN];

// ---------------- cp.async helpers ----------------
#define CP16(dst, src) \
    asm volatile("cp.async.cg.shared.global [%0], [%1], 16;" :: "r"(dst), "l"(src))
#define CPCOMMIT() asm volatile("cp.async.commit_group;")
#define CPWAIT1()  asm volatile("cp.async.wait_group 1;")
#define CPWAIT0()  asm volatile("cp.async.wait_group 0;")

__device__ __forceinline__ uint32_t smem_u32(const void* p) {
    uint32_t a;
    asm("{ .reg .u64 t; cvta.to.shared.u64 t, %1; cvt.u32.u64 %0, t; }" : "=r"(a) : "l"(p));
    return a;
}

// ---------------- threefry2x32 (bit-exact JAX PRNG) ----------------
__device__ __forceinline__ unsigned tf_rotl(unsigned v, int r) {
    return (v << r) | (v >> (32 - r));
}
__device__ __forceinline__ void threefry2x32(unsigned k0, unsigned k1,
                                             unsigned x0, unsigned x1,
                                             unsigned& o0, unsigned& o1) {
    unsigned ks2 = k0 ^ k1 ^ 0x1BD11BDAu;
    x0 += k0; x1 += k1;
#define TF_RND(r) { x0 += x1; x1 = tf_rotl(x1, r); x1 ^= x0; }
    TF_RND(13) TF_RND(15) TF_RND(26) TF_RND(6)
    x0 += k1;  x1 += ks2 + 1u;
    TF_RND(17) TF_RND(29) TF_RND(16) TF_RND(24)
    x0 += ks2; x1 += k0 + 2u;
    TF_RND(13) TF_RND(15) TF_RND(26) TF_RND(6)
    x0 += k0;  x1 += k1 + 3u;
    TF_RND(17) TF_RND(29) TF_RND(16) TF_RND(24)
    x0 += k1;  x1 += ks2 + 4u;
    TF_RND(13) TF_RND(15) TF_RND(26) TF_RND(6)
#undef TF_RND
    o0 = x0 + ks2;
    o1 = x1 + k0 + 5u;
}
__device__ __forceinline__ unsigned tf_bits32(unsigned ka, unsigned kb, unsigned i) {
    unsigned o0, o1;
    threefry2x32(ka, kb, 0u, i, o0, o1);
    return o0 ^ o1;
}

__global__ void rng_bits_kernel() {
    int id = blockIdx.x * blockDim.x + threadIdx.x;
    if (id >= 3 * 1792) return;
    int l = id / 1792, m = id % 1792;
    unsigned ka, kb;
    threefry2x32(0u, 42u, 0u, (unsigned)l, ka, kb);
    unsigned k1a, k1b, k2a, k2b;
    threefry2x32(ka, kb, 0u, 0u, k1a, k1b);
    threefry2x32(ka, kb, 0u, 1u, k2a, k2b);
    unsigned ub = tf_bits32(k1a, k1b, (unsigned)m);
    float u = __uint_as_float((ub >> 9) | 0x3f800000u) - 1.0f;
    g_scale[l][m] = fmaxf(0.5f, u + 0.5f);
    unsigned ha, hb_, la, lb_;
    threefry2x32(k2a, k2b, 0u, 0u, ha, hb_);
    threefry2x32(k2a, k2b, 0u, 1u, la, lb_);
    unsigned hbits = tf_bits32(ha, hb_, (unsigned)m);
    unsigned lbits = tf_bits32(la, lb_, (unsigned)m);
    unsigned off = ((hbits % 13u) * 9u + (lbits % 13u)) % 13u;
    g_len[l][m] = 19 + (int)off;
}

__global__ void rng_scan_kernel() {
    int id = blockIdx.x * blockDim.x + threadIdx.x;
    if (id >= 3 * BATCH) return;
    int l = id / BATCH, b = id % BATCH;
    int cnt = 0, off = 0;
    for (int s = 0; s < 7; s++) {
        int m = b * 7 + s;
        float scale = g_scale[l][m];
        int   L     = g_len[l][m];
        float Lm1   = (float)(L - 1);
        float offf  = (float)off;
        for (int j = 0; j < 64; j++) {
            float is = (float)j / scale;
            float fl = floorf(is);
            if (fl < Lm1 && (fl + offf) < 191.0f) {
                if (cnt < TLEN) {
                    g_src[l][b][cnt] = (int)(fl + offf);
                    g_lam[l][b][cnt] = is - fl;
                }
                cnt++;
            }
        }
        off += L;
    }
    for (int t = cnt; t < TLEN; t++) g_src[l][b][t] = -1;
}

// ---------------- prep_x (layer 0 only): fp32 (B,Csrc,192) -> fp16 hi/lo (B,200,Cpad) ----------------
__global__ __launch_bounds__(256)
void prep_x_kernel(const float* __restrict__ src, int Csrc, int Cpad,
                   __half* __restrict__ dhi, __half* __restrict__ dlo) {
    __shared__ float s[32][65];
    int c0 = blockIdx.x * 32;
    int t0 = blockIdx.y * 64;
    int b  = blockIdx.z;
    int tid = threadIdx.x;
    for (int i = tid; i < 32 * 64; i += 256) {
        int ci = i >> 6, tt = i & 63;
        int tsrc = t0 + tt - 2;
        float v = 0.f;
        int c = c0 + ci;
        if (c < Csrc && tsrc >= 0 && tsrc < TLEN)
            v = src[((size_t)b * Csrc + c) * TLEN + tsrc];
        s[ci][tt] = v;
    }
    __syncthreads();
    for (int i = tid; i < 64 * 32; i += 256) {
        int tdl = i >> 5, cl = i & 31;
        int td = t0 + tdl;
        if (td < TPAD) {
            float f = s[cl][tdl];
            __half hi = __float2half_rn(f);
            float lo = f - __half2float(hi);
            size_t o = ((size_t)b * TPAD + td) * Cpad + c0 + cl;
            dhi[o] = hi;
            dlo[o] = __float2half_rn(lo);
        }
    }
}

// ---------------- prep_w: fp32 (taps,Csrc,256) -> fp16 (taps,Cpad,256) ----------------
__global__ __launch_bounds__(256)
void prep_w_kernel(const float* __restrict__ w, __half* __restrict__ dst,
                   int taps, int Csrc, int Cpad) {
    int n = gridDim.x * blockDim.x;
    int total = taps * Cpad * 256;
    for (int i = blockIdx.x * blockDim.x + threadIdx.x; i < total; i += n) {
        int tap = i / (Cpad * 256);
        int rem = i % (Cpad * 256);
        int c = rem / 256, co = rem % 256;
        float v = (c < Csrc) ? w[((size_t)tap * Csrc + c) * 256 + co] : 0.f;
        dst[i] = __float2half_rn(v);
    }
}

// ---------------- prep_gw: gates weight (1,256,256) + bias ----------------
__global__ __launch_bounds__(256)
void prep_gw_kernel(const float* __restrict__ kf, const float* __restrict__ bf,
                    const float* __restrict__ kb, const float* __restrict__ bb) {
    int i = blockIdx.x * blockDim.x + threadIdx.x;
    if (i < 256 * 256) {
        int c = i / 256, nn = i % 256;
        float v = (nn < 128) ? kf[(size_t)c * 128 + nn] : kb[(size_t)c * 128 + (nn - 128)];
        g_wbg[i] = __float2half_rn(v);
        if (i < 256) g_gbias[i] = (i < 128) ? bf[i] : bb[i - 128];
    }
}

// ---------------- legacy-HMMA GEMM: W staged once per k-chunk, splits fused ----------------
#define A_SZ 5440

template <int TAPS>
__global__ __launch_bounds__(256)
void mma_kernel(const __half* __restrict__ Ahi, const __half* __restrict__ Alo,
                const __half* __restrict__ Wgt,
                const float* __restrict__ bias, float* __restrict__ out,
                int Cpad, int tap_offset, int mode) {
    constexpr int W_SZ  = TAPS * 32 * 272;
    constexpr int BUFSZ = W_SZ + 2 * A_SZ;

    extern __shared__ char dsm[];
    const uint32_t sb = smem_u32(dsm);

    const int bn = blockIdx.x;      // n tile (128 wide)
    const int bm = blockIdx.y;      // m tile (64 wide)
    const int bb = blockIdx.z;      // batch
    const int tid  = threadIdx.x;
    const int wid  = tid >> 5;
    const int lane = tid & 31;
    const int wm = wid >> 2;        // 0..1
    const int wn = wid & 3;         // 0..3
    const int t0 = bm * 64;
    const int n0 = bn * 128;

    float acc[2][4][4];
#pragma unroll
    for (int i = 0; i < 2; i++)
#pragma unroll
        for (int j = 0; j < 4; j++)
#pragma unroll
            for (int k = 0; k < 4; k++) acc[i][j][k] = 0.f;

    const int kchunks = Cpad >> 5;
    const int rs = Cpad >> 3;               // uint4 per activation row

    auto stage = [&](int it) {
        uint32_t buf = sb + (uint32_t)(it & 1) * BUFSZ;
        int k0 = it * 32;
        for (int i = tid; i < TAPS * 512; i += 256) {
            int tp = i >> 9, r = (i >> 4) & 31, q = i & 15;
            const uint4* srcW = (const uint4*)(Wgt + ((size_t)tp * Cpad + k0 + r) * 256 + n0);
            CP16(buf + (uint32_t)((tp * 32 + r) * 272 + q * 16), srcW + q);
        }
        const uint4* srcH = (const uint4*)(Ahi + ((size_t)bb * TPAD + t0) * Cpad + k0);
        const uint4* srcL = (const uint4*)(Alo + ((size_t)bb * TPAD + t0) * Cpad + k0);
        for (int i = tid; i < 272; i += 256) {
            int r = i >> 2, q = i & 3;
            CP16(buf + W_SZ + (uint32_t)(r * 80 + q * 16), srcH + (size_t)r * rs + q);
        }
        for (int i = tid; i < 272; i += 256) {
            int r = i >> 2, q = i & 3;
            CP16(buf + W_SZ + A_SZ + (uint32_t)(r * 80 + q * 16), srcL + (size_t)r * rs + q);
        }
    };

    stage(0);
    CPCOMMIT();

    for (int it = 0; it < kchunks; it++) {
        if (it + 1 < kchunks) {
            stage(it + 1);
            CPCOMMIT();
            CPWAIT1();
        } else {
            CPWAIT0();
        }
        __syncthreads();

        uint32_t buf  = sb + (uint32_t)(it & 1) * BUFSZ;
        uint32_t sahi = buf + W_SZ;
        uint32_t salo = sahi + A_SZ;

#pragma unroll
        for (int tp = 0; tp < TAPS; tp++) {
            int cshift = tap_offset + tp;
#pragma unroll
            for (int kstep = 0; kstep < 2; kstep++) {
                unsigned ah[2][4], al[2][4];
#pragma unroll
                for (int mt = 0; mt < 2; mt++) {
                    int row = wm * 32 + mt * 16 + cshift + (lane & 15);
                    int col = kstep * 16 + ((lane >> 4) * 8);
                    uint32_t adr_h = sahi + (uint32_t)(row * 80 + col * 2);
                    uint32_t adr_l = salo + (uint32_t)(row * 80 + col * 2);
                    asm volatile("ldmatrix.sync.aligned.m8n8.x4.shared.b16 {%0,%1,%2,%3}, [%4];"
                                 : "=r"(ah[mt][0]), "=r"(ah[mt][1]), "=r"(ah[mt][2]), "=r"(ah[mt][3])
                                 : "r"(adr_h));
                    asm volatile("ldmatrix.sync.aligned.m8n8.x4.shared.b16 {%0,%1,%2,%3}, [%4];"
                                 : "=r"(al[mt][0]), "=r"(al[mt][1]), "=r"(al[mt][2]), "=r"(al[mt][3])
                                 : "r"(adr_l));
                }
                unsigned bfr[4][2];
#pragma unroll
                for (int np = 0; np < 2; np++) {
                    int row = kstep * 16 + (lane & 15);
                    int col = wn * 32 + np * 16 + ((lane >= 16) ? 8 : 0);
                    uint32_t addr = buf + (uint32_t)((tp * 32 + row) * 272 + col * 2);
                    unsigned r0, r1, r2, r3;
                    asm volatile("ldmatrix.sync.aligned.m8n8.x4.trans.shared.b16 {%0,%1,%2,%3}, [%4];"
                                 : "=r"(r0), "=r"(r1), "=r"(r2), "=r"(r3)
                                 : "r"(addr));
                    bfr[np * 2 + 0][0] = r0; bfr[np * 2 + 0][1] = r1;
                    bfr[np * 2 + 1][0] = r2; bfr[np * 2 + 1][1] = r3;
                }
#pragma unroll
                for (int mt = 0; mt < 2; mt++)
#pragma unroll
                    for (int nt = 0; nt < 4; nt++) {
                        asm volatile(
                            "mma.sync.aligned.m16n8k16.row.col.f32.f16.f16.f32 "
                            "{%0,%1,%2,%3},{%4,%5,%6,%7},{%8,%9},{%0,%1,%2,%3};"
                            : "+f"(acc[mt][nt][0]), "+f"(acc[mt][nt][1]),
                              "+f"(acc[mt][nt][2]), "+f"(acc[mt][nt][3])
                            : "r"(ah[mt][0]), "r"(ah[mt][1]), "r"(ah[mt][2]), "r"(ah[mt][3]),
                              "r"(bfr[nt][0]), "r"(bfr[nt][1]));
                        asm volatile(
                            "mma.sync.aligned.m16n8k16.row.col.f32.f16.f16.f32 "
                            "{%0,%1,%2,%3},{%4,%5,%6,%7},{%8,%9},{%0,%1,%2,%3};"
                            : "+f"(acc[mt][nt][0]), "+f"(acc[mt][nt][1]),
                              "+f"(acc[mt][nt][2]), "+f"(acc[mt][nt][3])
                            : "r"(al[mt][0]), "r"(al[mt][1]), "r"(al[mt][2]), "r"(al[mt][3]),
                              "r"(bfr[nt][0]), "r"(bfr[nt][1]));
                    }
            }
        }
        __syncthreads();
    }

    // epilogue (+ fused partial GN stats in mode 0)
    int gid = lane >> 2, tig = lane & 3;
    float psum = 0.f, psum2 = 0.f;
#pragma unroll
    for (int mt = 0; mt < 2; mt++) {
#pragma unroll
        for (int nt = 0; nt < 4; nt++) {
            int t  = t0 + wm * 32 + mt * 16 + gid;
            int co = n0 + wn * 32 + nt * 8 + tig * 2;
            float bv0 = bias[co], bv1 = bias[co + 1];
            float v0 = acc[mt][nt][0] + bv0;
            float v1 = acc[mt][nt][1] + bv1;
            float v2 = acc[mt][nt][2] + bv0;
            float v3 = acc[mt][nt][3] + bv1;
            if (mode == 0) {
                float* yp0 = out + ((size_t)bb * 256 + co) * TLEN;
                float* yp1 = yp0 + TLEN;
                yp0[t]     = v0;
                yp1[t]     = v1;
                yp0[t + 8] = v2;
                yp1[t + 8] = v3;
                psum  += v0 + v1 + v2 + v3;
                psum2 = fmaf(v0, v0, fmaf(v1, v1, fmaf(v2, v2, fmaf(v3, v3, psum2))));
            } else {
                // gate-interleaved pre layout: col (g&31)*4 + (g>>5)
                int dir0 = co >> 7, g0 = co & 127;
                int dir1 = (co + 1) >> 7, g1 = (co + 1) & 127;
                int c0i = (g0 & 31) * 4 + (g0 >> 5);
                int c1i = (g1 & 31) * 4 + (g1 >> 5);
                size_t r0 = ((size_t)(dir0 * BATCH + bb) * TLEN + t) * NGATE + c0i;
                size_t r1 = ((size_t)(dir1 * BATCH + bb) * TLEN + t) * NGATE + c1i;
                out[r0] = v0;
                out[r1] = v1;
                size_t r2 = ((size_t)(dir0 * BATCH + bb) * TLEN + t + 8) * NGATE + c0i;
                size_t r3 = ((size_t)(dir1 * BATCH + bb) * TLEN + t + 8) * NGATE + c1i;
                out[r2] = v2;
                out[r3] = v3;
            }
        }
    }
    if (mode == 0) {
        float* red = (float*)dsm;      // reuse staging smem (all loads done)
        __syncthreads();
        red[tid] = psum;
        red[256 + tid] = psum2;
        __syncthreads();
        for (int k = 128; k > 0; k >>= 1) {
            if (tid < k) {
                red[tid] += red[tid + k];
                red[256 + tid] += red[256 + tid + k];
            }
            __syncthreads();
        }
        if (tid == 0) {
            g_psum [bb][bm * 2 + bn] = red[0];
            g_psum2[bb][bm * 2 + bn] = red[256];
        }
    }
}

// ---------------- fused GN + ReLU + interp gather + fp16 hi/lo transpose ----------------
__global__ __launch_bounds__(256)
void gather_fuse_kernel(const float* __restrict__ y,
                        __half* __restrict__ dhi, __half* __restrict__ dlo,
                        const float* __restrict__ gamma, const float* __restrict__ beta,
                        int layer) {
    __shared__ float s[TLEN][33];
    int b = blockIdx.x, cz = blockIdx.y;
    int c0 = cz * 32;
    int tid = threadIdx.x;

    float ts = 0.f, tq = 0.f;
#pragma unroll
    for (int i = 0; i < 6; i++) { ts += g_psum[b][i]; tq += g_psum2[b][i]; }
    const float inv_n = 1.0f / (float)(CENC * TLEN);
    float mean = ts * inv_n;
    float istd = rsqrtf(fmaxf(tq * inv_n - mean * mean, 0.f) + 1e-5f);

    for (int i = tid; i < 32 * TLEN; i += 256) {
        int ci = i / TLEN;
        int t = i % TLEN;
        int src = g_src[layer][b][t];
        float v = 0.f;
        if (src >= 0) {
            float lam = g_lam[layer][b][t];
            const float* yr = y + ((size_t)b * CENC + c0 + ci) * TLEN;
            float r0 = fmaxf((yr[src]     - mean) * istd * gamma[src]     + beta[src],     0.f);
            float r1 = fmaxf((yr[src + 1] - mean) * istd * gamma[src + 1] + beta[src + 1], 0.f);
            v = (1.f - lam) * r0 + lam * r1;
        }
        s[t][ci] = v;
    }
    __syncthreads();

    for (int i = tid; i < TLEN * 32; i += 256) {
        int t = i >> 5, ci = i & 31;
        float f = s[t][ci];
        __half hi = __float2half_rn(f);
        float lo = f - __half2float(hi);
        size_t o = ((size_t)b * TPAD + t + 2) * CENC + c0 + ci;
        dhi[o] = hi;
        dlo[o] = __float2half_rn(lo);
    }
    if (tid < 256) {
        const int padrows[8] = {0, 1, 194, 195, 196, 197, 198, 199};
        int pr = padrows[tid >> 5], ci = tid & 31;
        size_t o = ((size_t)b * TPAD + pr) * CENC + c0 + ci;
        dhi[o] = __float2half_rn(0.f);
        dlo[o] = __float2half_rn(0.f);
    }
}

// ---------------- LSTM recurrence: float4 gate layout, 128-thread CTAs ----------------
__device__ __forceinline__ float sigm(float x) { return 1.f / (1.f + expf(-x)); }

__global__ __launch_bounds__(128)
void lstm_kernel(const float* __restrict__ pre,
                 const float* __restrict__ rf, const float* __restrict__ rb,
                 float* __restrict__ out) {
    __shared__ __align__(16) float4 Rs4[32][32];
    int dir = blockIdx.y;
    const float* R = dir ? rb : rf;
    for (int i = threadIdx.x; i < 32 * 32; i += 128) {
        int j = i >> 5, l = i & 31;
        Rs4[j][l] = make_float4(R[j * 128 + l],      R[j * 128 + 32 + l],
                                R[j * 128 + 64 + l], R[j * 128 + 96 + l]);
    }
    __syncthreads();

    int warp = threadIdx.x >> 5, lane = threadIdx.x & 31;
    int b = blockIdx.x * 4 + warp;
    float h = 0.f, c = 0.f;
    const float4* preb = (const float4*)(pre + (((size_t)dir * BATCH + b) * TLEN) * NGATE);

    for (int s = 0; s < TLEN; s++) {
        int t = dir ? (TLEN - 1 - s) : s;
        float4 z = preb[(size_t)t * 32 + lane];
#pragma unroll
        for (int j = 0; j < 32; j++) {
            float hj = __shfl_sync(0xffffffffu, h, j);
            float4 r = Rs4[j][lane];
            z.x = fmaf(hj, r.x, z.x);
            z.y = fmaf(hj, r.y, z.y);
            z.z = fmaf(hj, r.z, z.z);
            z.w = fmaf(hj, r.w, z.w);
        }
        c = sigm(z.y) * c + sigm(z.x) * tanhf(z.z);
        h = sigm(z.w) * tanhf(c);
        out[((size_t)b * TLEN + t) * 64 + dir * 32 + lane] = h;
    }
}

// ---------------- launch ----------------
extern "C" void kernel_launch(void* const* d_in, const int* in_sizes, int n_in,
                              void* d_out, int out_size) {
    const float* x   = (const float*)d_in[0];
    const float* w0  = (const float*)d_in[1];
    const float* b0  = (const float*)d_in[2];
    const float* w1  = (const float*)d_in[3];
    const float* b1  = (const float*)d_in[4];
    const float* w2  = (const float*)d_in[5];
    const float* b2  = (const float*)d_in[6];
    const float* g0  = (const float*)d_in[7];
    const float* be0 = (const float*)d_in[8];
    const float* g1  = (const float*)d_in[9];
    const float* be1 = (const float*)d_in[10];
    const float* g2  = (const float*)d_in[11];
    const float* be2 = (const float*)d_in[12];
    const float* kf  = (const float*)d_in[13];
    const float* rf  = (const float*)d_in[14];
    const float* bf  = (const float*)d_in[15];
    const float* kb  = (const float*)d_in[16];
    const float* rb  = (const float*)d_in[17];
    const float* bb  = (const float*)d_in[18];

    float *bufy, *pre, *gbias;
    __half *axh, *axl, *wb0, *wb1, *wb2, *wbg;
    cudaGetSymbolAddress((void**)&bufy, g_bufy);
    cudaGetSymbolAddress((void**)&pre,  g_pre);
    cudaGetSymbolAddress((void**)&gbias, g_gbias);
    cudaGetSymbolAddress((void**)&axh, g_ax_hi);
    cudaGetSymbolAddress((void**)&axl, g_ax_lo);
    cudaGetSymbolAddress((void**)&wb0, g_wb0);
    cudaGetSymbolAddress((void**)&wb1, g_wb1);
    cudaGetSymbolAddress((void**)&wb2, g_wb2);
    cudaGetSymbolAddress((void**)&wbg, g_wbg);

    const int SMEM5 = 2 * (5 * 32 * 272 + 2 * A_SZ);   // 108800
    const int SMEM1 = 2 * (1 * 32 * 272 + 2 * A_SZ);   // 39168
    cudaFuncSetAttribute(mma_kernel<5>, cudaFuncAttributeMaxDynamicSharedMemorySize, SMEM5);
    cudaFuncSetAttribute(mma_kernel<1>, cudaFuncAttributeMaxDynamicSharedMemorySize, SMEM1);

    // independent preprocessing — all up front
    rng_bits_kernel<<<21, 256>>>();
    rng_scan_kernel<<<3, 256>>>();
    prep_w_kernel<<<288, 256>>>(w0, wb0, 5, 257, 288);
    prep_w_kernel<<<256, 256>>>(w1, wb1, 5, 256, 256);
    prep_w_kernel<<<256, 256>>>(w2, wb2, 5, 256, 256);
    prep_gw_kernel<<<256, 256>>>(kf, bf, kb, bb);
    prep_x_kernel<<<dim3(9, 4, BATCH), 256>>>(x, 257, 288, axh, axl);

    dim3 gmma(2, 3, BATCH);
    dim3 ggath(BATCH, 8);

    // layer 0 (Cpad=288)
    mma_kernel<5><<<gmma, 256, SMEM5>>>(axh, axl, wb0, b0, bufy, 288, 0, 0);
    gather_fuse_kernel<<<ggath, 256>>>(bufy, axh, axl, g0, be0, 0);
    // layer 1 (Cpad=256)
    mma_kernel<5><<<gmma, 256, SMEM5>>>(axh, axl, wb1, b1, bufy, 256, 0, 0);
    gather_fuse_kernel<<<ggath, 256>>>(bufy, axh, axl, g1, be1, 1);
    // layer 2
    mma_kernel<5><<<gmma, 256, SMEM5>>>(axh, axl, wb2, b2, bufy, 256, 0, 0);
    gather_fuse_kernel<<<ggath, 256>>>(bufy, axh, axl, g2, be2, 2);

    // gates GEMM: taps=1 at offset 2 (time t), mode 1 (gate-interleaved)
    mma_kernel<1><<<gmma, 256, SMEM1>>>(axh, axl, wbg, gbias, pre, 256, 2, 1);

    lstm_kernel<<<dim3(64, 2), 128>>>(pre, rf, rb, (float*)d_out);
}

// round 13
// speedup vs baseline: 1.4285x; 1.2724x over previous
#include <cuda_runtime.h>
#include <cuda_fp16.h>
#include <math.h>
#include <stdint.h>

#define BATCH 256
#define TLEN  192
#define CENC  256
#define NGATE 128
#define NECK  32
#define TPAD  200
#define CPAD_MAX 288

// ---------------- scratch ----------------
__device__ float g_bufy[(size_t)BATCH * CENC * TLEN];            // conv output (B,C,T)
__device__ float g_pre [(size_t)2 * BATCH * TLEN * NGATE];       // lstm pre-gates (gate-interleaved)
__device__ __half g_ax[(size_t)BATCH * TPAD * CPAD_MAX];         // fp16 activations
__device__ __half g_wb0[(size_t)5 * 288 * 256];                  // layer0 weights (tap,c,co)
__device__ __half g_wb1[(size_t)5 * 256 * 256];
__device__ __half g_wb2[(size_t)5 * 256 * 256];
__device__ __half g_wbg[(size_t)256 * 256];                      // gates weights
__device__ float g_gbias[256];
__device__ float g_psum [BATCH][6];                              // per-tile partial sums
__device__ float g_psum2[BATCH][6];
__device__ float g_scale[3][1792];
__device__ int   g_len  [3][1792];
__device__ int   g_src  [3][BATCH][TLEN];
__device__ float g_lam  [3][BATCH][TLEN];

// ---------------- cp.async helpers ----------------
#define CP16(dst, src) \
    asm volatile("cp.async.cg.shared.global [%0], [%1], 16;" :: "r"(dst), "l"(src))
#define CPCOMMIT() asm volatile("cp.async.commit_group;")
#define CPWAIT1()  asm volatile("cp.async.wait_group 1;")
#define CPWAIT0()  asm volatile("cp.async.wait_group 0;")

__device__ __forceinline__ uint32_t smem_u32(const void* p) {
    uint32_t a;
    asm("{ .reg .u64 t; cvta.to.shared.u64 t, %1; cvt.u32.u64 %0, t; }" : "=r"(a) : "l"(p));
    return a;
}

// ---------------- threefry2x32 (bit-exact JAX PRNG) ----------------
__device__ __forceinline__ unsigned tf_rotl(unsigned v, int r) {
    return (v << r) | (v >> (32 - r));
}
__device__ __forceinline__ void threefry2x32(unsigned k0, unsigned k1,
                                             unsigned x0, unsigned x1,
                                             unsigned& o0, unsigned& o1) {
    unsigned ks2 = k0 ^ k1 ^ 0x1BD11BDAu;
    x0 += k0; x1 += k1;
#define TF_RND(r) { x0 += x1; x1 = tf_rotl(x1, r); x1 ^= x0; }
    TF_RND(13) TF_RND(15) TF_RND(26) TF_RND(6)
    x0 += k1;  x1 += ks2 + 1u;
    TF_RND(17) TF_RND(29) TF_RND(16) TF_RND(24)
    x0 += ks2; x1 += k0 + 2u;
    TF_RND(13) TF_RND(15) TF_RND(26) TF_RND(6)
    x0 += k0;  x1 += k1 + 3u;
    TF_RND(17) TF_RND(29) TF_RND(16) TF_RND(24)
    x0 += k1;  x1 += ks2 + 4u;
    TF_RND(13) TF_RND(15) TF_RND(26) TF_RND(6)
#undef TF_RND
    o0 = x0 + ks2;
    o1 = x1 + k0 + 5u;
}
__device__ __forceinline__ unsigned tf_bits32(unsigned ka, unsigned kb, unsigned i) {
    unsigned o0, o1;
    threefry2x32(ka, kb, 0u, i, o0, o1);
    return o0 ^ o1;
}

__global__ void rng_bits_kernel() {
    int id = blockIdx.x * blockDim.x + threadIdx.x;
    if (id >= 3 * 1792) return;
    int l = id / 1792, m = id % 1792;
    unsigned ka, kb;
    threefry2x32(0u, 42u, 0u, (unsigned)l, ka, kb);
    unsigned k1a, k1b, k2a, k2b;
    threefry2x32(ka, kb, 0u, 0u, k1a, k1b);
    threefry2x32(ka, kb, 0u, 1u, k2a, k2b);
    unsigned ub = tf_bits32(k1a, k1b, (unsigned)m);
    float u = __uint_as_float((ub >> 9) | 0x3f800000u) - 1.0f;
    g_scale[l][m] = fmaxf(0.5f, u + 0.5f);
    unsigned ha, hb_, la, lb_;
    threefry2x32(k2a, k2b, 0u, 0u, ha, hb_);
    threefry2x32(k2a, k2b, 0u, 1u, la, lb_);
    unsigned hbits = tf_bits32(ha, hb_, (unsigned)m);
    unsigned lbits = tf_bits32(la, lb_, (unsigned)m);
    unsigned off = ((hbits % 13u) * 9u + (lbits % 13u)) % 13u;
    g_len[l][m] = 19 + (int)off;
}

__global__ void rng_scan_kernel() {
    int id = blockIdx.x * blockDim.x + threadIdx.x;
    if (id >= 3 * BATCH) return;
    int l = id / BATCH, b = id % BATCH;
    int cnt = 0, off = 0;
    for (int s = 0; s < 7; s++) {
        int m = b * 7 + s;
        float scale = g_scale[l][m];
        int   L     = g_len[l][m];
        float Lm1   = (float)(L - 1);
        float offf  = (float)off;
        for (int j = 0; j < 64; j++) {
            float is = (float)j / scale;
            float fl = floorf(is);
            if (fl < Lm1 && (fl + offf) < 191.0f) {
                if (cnt < TLEN) {
                    g_src[l][b][cnt] = (int)(fl + offf);
                    g_lam[l][b][cnt] = is - fl;
                }
                cnt++;
            }
        }
        off += L;
    }
    for (int t = cnt; t < TLEN; t++) g_src[l][b][t] = -1;
}

// ---------------- prep_x (layer 0 only): fp32 (B,Csrc,192) -> fp16 (B,200,Cpad) ----------------
__global__ __launch_bounds__(256)
void prep_x_kernel(const float* __restrict__ src, int Csrc, int Cpad,
                   __half* __restrict__ dst) {
    __shared__ float s[32][65];
    int c0 = blockIdx.x * 32;
    int t0 = blockIdx.y * 64;
    int b  = blockIdx.z;
    int tid = threadIdx.x;
    for (int i = tid; i < 32 * 64; i += 256) {
        int ci = i >> 6, tt = i & 63;
        int tsrc = t0 + tt - 2;
        float v = 0.f;
        int c = c0 + ci;
        if (c < Csrc && tsrc >= 0 && tsrc < TLEN)
            v = src[((size_t)b * Csrc + c) * TLEN + tsrc];
        s[ci][tt] = v;
    }
    __syncthreads();
    for (int i = tid; i < 64 * 32; i += 256) {
        int tdl = i >> 5, cl = i & 31;
        int td = t0 + tdl;
        if (td < TPAD)
            dst[((size_t)b * TPAD + td) * Cpad + c0 + cl] = __float2half_rn(s[cl][tdl]);
    }
}

// ---------------- prep_w: fp32 (taps,Csrc,256) -> fp16 (taps,Cpad,256) ----------------
__global__ __launch_bounds__(256)
void prep_w_kernel(const float* __restrict__ w, __half* __restrict__ dst,
                   int taps, int Csrc, int Cpad) {
    int n = gridDim.x * blockDim.x;
    int total = taps * Cpad * 256;
    for (int i = blockIdx.x * blockDim.x + threadIdx.x; i < total; i += n) {
        int tap = i / (Cpad * 256);
        int rem = i % (Cpad * 256);
        int c = rem / 256, co = rem % 256;
        float v = (c < Csrc) ? w[((size_t)tap * Csrc + c) * 256 + co] : 0.f;
        dst[i] = __float2half_rn(v);
    }
}

// ---------------- prep_gw: gates weight (1,256,256) + bias ----------------
__global__ __launch_bounds__(256)
void prep_gw_kernel(const float* __restrict__ kf, const float* __restrict__ bf,
                    const float* __restrict__ kb, const float* __restrict__ bb) {
    int i = blockIdx.x * blockDim.x + threadIdx.x;
    if (i < 256 * 256) {
        int c = i / 256, nn = i % 256;
        float v = (nn < 128) ? kf[(size_t)c * 128 + nn] : kb[(size_t)c * 128 + (nn - 128)];
        g_wbg[i] = __float2half_rn(v);
        if (i < 256) g_gbias[i] = (i < 128) ? bf[i] : bb[i - 128];
    }
}

// ---------------- legacy-HMMA GEMM: single fp16 pass ----------------
#define A_SZ 5440

template <int TAPS>
__global__ __launch_bounds__(256)
void mma_kernel(const __half* __restrict__ Ax,
                const __half* __restrict__ Wgt,
                const float* __restrict__ bias, float* __restrict__ out,
                int Cpad, int tap_offset, int mode) {
    constexpr int W_SZ  = TAPS * 32 * 272;
    constexpr int BUFSZ = W_SZ + A_SZ;

    extern __shared__ char dsm[];
    const uint32_t sb = smem_u32(dsm);

    const int bn = blockIdx.x;      // n tile (128 wide)
    const int bm = blockIdx.y;      // m tile (64 wide)
    const int bb = blockIdx.z;      // batch
    const int tid  = threadIdx.x;
    const int wid  = tid >> 5;
    const int lane = tid & 31;
    const int wm = wid >> 2;        // 0..1
    const int wn = wid & 3;         // 0..3
    const int t0 = bm * 64;
    const int n0 = bn * 128;

    float acc[2][4][4];
#pragma unroll
    for (int i = 0; i < 2; i++)
#pragma unroll
        for (int j = 0; j < 4; j++)
#pragma unroll
            for (int k = 0; k < 4; k++) acc[i][j][k] = 0.f;

    const int kchunks = Cpad >> 5;
    const int rs = Cpad >> 3;               // uint4 per activation row

    auto stage = [&](int it) {
        uint32_t buf = sb + (uint32_t)(it & 1) * BUFSZ;
        int k0 = it * 32;
        for (int i = tid; i < TAPS * 512; i += 256) {
            int tp = i >> 9, r = (i >> 4) & 31, q = i & 15;
            const uint4* srcW = (const uint4*)(Wgt + ((size_t)tp * Cpad + k0 + r) * 256 + n0);
            CP16(buf + (uint32_t)((tp * 32 + r) * 272 + q * 16), srcW + q);
        }
        const uint4* srcA = (const uint4*)(Ax + ((size_t)bb * TPAD + t0) * Cpad + k0);
        for (int i = tid; i < 272; i += 256) {
            int r = i >> 2, q = i & 3;
            CP16(buf + W_SZ + (uint32_t)(r * 80 + q * 16), srcA + (size_t)r * rs + q);
        }
    };

    stage(0);
    CPCOMMIT();

    for (int it = 0; it < kchunks; it++) {
        if (it + 1 < kchunks) {
            stage(it + 1);
            CPCOMMIT();
            CPWAIT1();
        } else {
            CPWAIT0();
        }
        __syncthreads();

        uint32_t buf = sb + (uint32_t)(it & 1) * BUFSZ;
        uint32_t sa  = buf + W_SZ;

#pragma unroll
        for (int tp = 0; tp < TAPS; tp++) {
            int cshift = tap_offset + tp;
#pragma unroll
            for (int kstep = 0; kstep < 2; kstep++) {
                unsigned ah[2][4];
#pragma unroll
                for (int mt = 0; mt < 2; mt++) {
                    int row = wm * 32 + mt * 16 + cshift + (lane & 15);
                    int col = kstep * 16 + ((lane >> 4) * 8);
                    uint32_t adr = sa + (uint32_t)(row * 80 + col * 2);
                    asm volatile("ldmatrix.sync.aligned.m8n8.x4.shared.b16 {%0,%1,%2,%3}, [%4];"
                                 : "=r"(ah[mt][0]), "=r"(ah[mt][1]), "=r"(ah[mt][2]), "=r"(ah[mt][3])
                                 : "r"(adr));
                }
                unsigned bfr[4][2];
#pragma unroll
                for (int np = 0; np < 2; np++) {
                    int row = kstep * 16 + (lane & 15);
                    int col = wn * 32 + np * 16 + ((lane >= 16) ? 8 : 0);
                    uint32_t addr = buf + (uint32_t)((tp * 32 + row) * 272 + col * 2);
                    unsigned r0, r1, r2, r3;
                    asm volatile("ldmatrix.sync.aligned.m8n8.x4.trans.shared.b16 {%0,%1,%2,%3}, [%4];"
                                 : "=r"(r0), "=r"(r1), "=r"(r2), "=r"(r3)
                                 : "r"(addr));
                    bfr[np * 2 + 0][0] = r0; bfr[np * 2 + 0][1] = r1;
                    bfr[np * 2 + 1][0] = r2; bfr[np * 2 + 1][1] = r3;
                }
#pragma unroll
                for (int mt = 0; mt < 2; mt++)
#pragma unroll
                    for (int nt = 0; nt < 4; nt++) {
                        asm volatile(
                            "mma.sync.aligned.m16n8k16.row.col.f32.f16.f16.f32 "
                            "{%0,%1,%2,%3},{%4,%5,%6,%7},{%8,%9},{%0,%1,%2,%3};"
                            : "+f"(acc[mt][nt][0]), "+f"(acc[mt][nt][1]),
                              "+f"(acc[mt][nt][2]), "+f"(acc[mt][nt][3])
                            : "r"(ah[mt][0]), "r"(ah[mt][1]), "r"(ah[mt][2]), "r"(ah[mt][3]),
                              "r"(bfr[nt][0]), "r"(bfr[nt][1]));
                    }
            }
        }
        __syncthreads();
    }

    // epilogue (+ fused partial GN stats in mode 0)
    int gid = lane >> 2, tig = lane & 3;
    float psum = 0.f, psum2 = 0.f;
#pragma unroll
    for (int mt = 0; mt < 2; mt++) {
#pragma unroll
        for (int nt = 0; nt < 4; nt++) {
            int t  = t0 + wm * 32 + mt * 16 + gid;
            int co = n0 + wn * 32 + nt * 8 + tig * 2;
            float bv0 = bias[co], bv1 = bias[co + 1];
            float v0 = acc[mt][nt][0] + bv0;
            float v1 = acc[mt][nt][1] + bv1;
            float v2 = acc[mt][nt][2] + bv0;
            float v3 = acc[mt][nt][3] + bv1;
            if (mode == 0) {
                float* yp0 = out + ((size_t)bb * 256 + co) * TLEN;
                float* yp1 = yp0 + TLEN;
                yp0[t]     = v0;
                yp1[t]     = v1;
                yp0[t + 8] = v2;
                yp1[t + 8] = v3;
                psum  += v0 + v1 + v2 + v3;
                psum2 = fmaf(v0, v0, fmaf(v1, v1, fmaf(v2, v2, fmaf(v3, v3, psum2))));
            } else {
                // gate-interleaved pre layout: col (g&31)*4 + (g>>5)
                int dir0 = co >> 7, g0 = co & 127;
                int dir1 = (co + 1) >> 7, g1 = (co + 1) & 127;
                int c0i = (g0 & 31) * 4 + (g0 >> 5);
                int c1i = (g1 & 31) * 4 + (g1 >> 5);
                size_t r0 = ((size_t)(dir0 * BATCH + bb) * TLEN + t) * NGATE + c0i;
                size_t r1 = ((size_t)(dir1 * BATCH + bb) * TLEN + t) * NGATE + c1i;
                out[r0] = v0;
                out[r1] = v1;
                size_t r2 = ((size_t)(dir0 * BATCH + bb) * TLEN + t + 8) * NGATE + c0i;
                size_t r3 = ((size_t)(dir1 * BATCH + bb) * TLEN + t + 8) * NGATE + c1i;
                out[r2] = v2;
                out[r3] = v3;
            }
        }
    }
    if (mode == 0) {
        float* red = (float*)dsm;      // reuse staging smem (all loads done)
        __syncthreads();
        red[tid] = psum;
        red[256 + tid] = psum2;
        __syncthreads();
        for (int k = 128; k > 0; k >>= 1) {
            if (tid < k) {
                red[tid] += red[tid + k];
                red[256 + tid] += red[256 + tid + k];
            }
            __syncthreads();
        }
        if (tid == 0) {
            g_psum [bb][bm * 2 + bn] = red[0];
            g_psum2[bb][bm * 2 + bn] = red[256];
        }
    }
}

// ---------------- fused GN + ReLU + interp gather + fp16 transpose ----------------
__global__ __launch_bounds__(256)
void gather_fuse_kernel(const float* __restrict__ y,
                        __half* __restrict__ dst,
                        const float* __restrict__ gamma, const float* __restrict__ beta,
                        int layer) {
    __shared__ float s[TLEN][33];
    int b = blockIdx.x, cz = blockIdx.y;
    int c0 = cz * 32;
    int tid = threadIdx.x;

    float ts = 0.f, tq = 0.f;
#pragma unroll
    for (int i = 0; i < 6; i++) { ts += g_psum[b][i]; tq += g_psum2[b][i]; }
    const float inv_n = 1.0f / (float)(CENC * TLEN);
    float mean = ts * inv_n;
    float istd = rsqrtf(fmaxf(tq * inv_n - mean * mean, 0.f) + 1e-5f);

    for (int i = tid; i < 32 * TLEN; i += 256) {
        int ci = i / TLEN;
        int t = i % TLEN;
        int src = g_src[layer][b][t];
        float v = 0.f;
        if (src >= 0) {
            float lam = g_lam[layer][b][t];
            const float* yr = y + ((size_t)b * CENC + c0 + ci) * TLEN;
            float r0 = fmaxf((yr[src]     - mean) * istd * gamma[src]     + beta[src],     0.f);
            float r1 = fmaxf((yr[src + 1] - mean) * istd * gamma[src + 1] + beta[src + 1], 0.f);
            v = (1.f - lam) * r0 + lam * r1;
        }
        s[t][ci] = v;
    }
    __syncthreads();

    for (int i = tid; i < TLEN * 32; i += 256) {
        int t = i >> 5, ci = i & 31;
        dst[((size_t)b * TPAD + t + 2) * CENC + c0 + ci] = __float2half_rn(s[t][ci]);
    }
    if (tid < 256) {
        const int padrows[8] = {0, 1, 194, 195, 196, 197, 198, 199};
        int pr = padrows[tid >> 5], ci = tid & 31;
        dst[((size_t)b * TPAD + pr) * CENC + c0 + ci] = __float2half_rn(0.f);
    }
}

// ---------------- LSTM recurrence: float4 gate layout, 128-thread CTAs ----------------
__device__ __forceinline__ float sigm(float x) { return 1.f / (1.f + expf(-x)); }

__global__ __launch_bounds__(128)
void lstm_kernel(const float* __restrict__ pre,
                 const float* __restrict__ rf, const float* __restrict__ rb,
                 float* __restrict__ out) {
    __shared__ __align__(16) float4 Rs4[32][32];
    int dir = blockIdx.y;
    const float* R = dir ? rb : rf;
    for (int i = threadIdx.x; i < 32 * 32; i += 128) {
        int j = i >> 5, l = i & 31;
        Rs4[j][l] = make_float4(R[j * 128 + l],      R[j * 128 + 32 + l],
                                R[j * 128 + 64 + l], R[j * 128 + 96 + l]);
    }
    __syncthreads();

    int warp = threadIdx.x >> 5, lane = threadIdx.x & 31;
    int b = blockIdx.x * 4 + warp;
    float h = 0.f, c = 0.f;
    const float4* preb = (const float4*)(pre + (((size_t)dir * BATCH + b) * TLEN) * NGATE);

    for (int s = 0; s < TLEN; s++) {
        int t = dir ? (TLEN - 1 - s) : s;
        float4 z = preb[(size_t)t * 32 + lane];
#pragma unroll
        for (int j = 0; j < 32; j++) {
            float hj = __shfl_sync(0xffffffffu, h, j);
            float4 r = Rs4[j][lane];
            z.x = fmaf(hj, r.x, z.x);
            z.y = fmaf(hj, r.y, z.y);
            z.z = fmaf(hj, r.z, z.z);
            z.w = fmaf(hj, r.w, z.w);
        }
        c = sigm(z.y) * c + sigm(z.x) * tanhf(z.z);
        h = sigm(z.w) * tanhf(c);
        out[((size_t)b * TLEN + t) * 64 + dir * 32 + lane] = h;
    }
}

// ---------------- launch ----------------
extern "C" void kernel_launch(void* const* d_in, const int* in_sizes, int n_in,
                              void* d_out, int out_size) {
    const float* x   = (const float*)d_in[0];
    const float* w0  = (const float*)d_in[1];
    const float* b0  = (const float*)d_in[2];
    const float* w1  = (const float*)d_in[3];
    const float* b1  = (const float*)d_in[4];
    const float* w2  = (const float*)d_in[5];
    const float* b2  = (const float*)d_in[6];
    const float* g0  = (const float*)d_in[7];
    const float* be0 = (const float*)d_in[8];
    const float* g1  = (const float*)d_in[9];
    const float* be1 = (const float*)d_in[10];
    const float* g2  = (const float*)d_in[11];
    const float* be2 = (const float*)d_in[12];
    const float* kf  = (const float*)d_in[13];
    const float* rf  = (const float*)d_in[14];
    const float* bf  = (const float*)d_in[15];
    const float* kb  = (const float*)d_in[16];
    const float* rb  = (const float*)d_in[17];
    const float* bb  = (const float*)d_in[18];

    float *bufy, *pre, *gbias;
    __half *ax, *wb0, *wb1, *wb2, *wbg;
    cudaGetSymbolAddress((void**)&bufy, g_bufy);
    cudaGetSymbolAddress((void**)&pre,  g_pre);
    cudaGetSymbolAddress((void**)&gbias, g_gbias);
    cudaGetSymbolAddress((void**)&ax,  g_ax);
    cudaGetSymbolAddress((void**)&wb0, g_wb0);
    cudaGetSymbolAddress((void**)&wb1, g_wb1);
    cudaGetSymbolAddress((void**)&wb2, g_wb2);
    cudaGetSymbolAddress((void**)&wbg, g_wbg);

    const int SMEM5 = 2 * (5 * 32 * 272 + A_SZ);   // 97920
    const int SMEM1 = 2 * (1 * 32 * 272 + A_SZ);   // 28288
    cudaFuncSetAttribute(mma_kernel<5>, cudaFuncAttributeMaxDynamicSharedMemorySize, SMEM5);
    cudaFuncSetAttribute(mma_kernel<1>, cudaFuncAttributeMaxDynamicSharedMemorySize, SMEM1);

    // independent preprocessing — all up front
    rng_bits_kernel<<<21, 256>>>();
    rng_scan_kernel<<<3, 256>>>();
    prep_w_kernel<<<288, 256>>>(w0, wb0, 5, 257, 288);
    prep_w_kernel<<<256, 256>>>(w1, wb1, 5, 256, 256);
    prep_w_kernel<<<256, 256>>>(w2, wb2, 5, 256, 256);
    prep_gw_kernel<<<256, 256>>>(kf, bf, kb, bb);
    prep_x_kernel<<<dim3(9, 4, BATCH), 256>>>(x, 257, 288, ax);

    dim3 gmma(2, 3, BATCH);
    dim3 ggath(BATCH, 8);

    // layer 0 (Cpad=288)
    mma_kernel<5><<<gmma, 256, SMEM5>>>(ax, wb0, b0, bufy, 288, 0, 0);
    gather_fuse_kernel<<<ggath, 256>>>(bufy, ax, g0, be0, 0);
    // layer 1 (Cpad=256)
    mma_kernel<5><<<gmma, 256, SMEM5>>>(ax, wb1, b1, bufy, 256, 0, 0);
    gather_fuse_kernel<<<ggath, 256>>>(bufy, ax, g1, be1, 1);
    // layer 2
    mma_kernel<5><<<gmma, 256, SMEM5>>>(ax, wb2, b2, bufy, 256, 0, 0);
    gather_fuse_kernel<<<ggath, 256>>>(bufy, ax, g2, be2, 2);

    // gates GEMM: taps=1 at offset 2 (time t), mode 1 (gate-interleaved)
    mma_kernel<1><<<gmma, 256, SMEM1>>>(ax, wbg, gbias, pre, 256, 2, 1);

    lstm_kernel<<<dim3(64, 2), 128>>>(pre, rf, rb, (float*)d_out);
}

// round 14
// speedup vs baseline: 1.4618x; 1.0233x over previous
#include <cuda_runtime.h>
#include <cuda_fp16.h>
#include <math.h>
#include <stdint.h>

#define BATCH 256
#define TLEN  192
#define CENC  256
#define NGATE 128
#define NECK  32
#define TPAD  200
#define CPAD_MAX 288

// ---------------- scratch ----------------
__device__ float g_bufy[(size_t)BATCH * CENC * TLEN];            // conv output (B,C,T)
__device__ float g_pre [(size_t)2 * BATCH * TLEN * NGATE];       // lstm pre-gates (gate-interleaved)
__device__ __half g_ax[(size_t)BATCH * TPAD * CPAD_MAX];         // fp16 activations
__device__ __half g_wb0[(size_t)5 * 288 * 256];                  // layer0 weights (tap,c,co)
__device__ __half g_wb1[(size_t)5 * 256 * 256];
__device__ __half g_wb2[(size_t)5 * 256 * 256];
__device__ __half g_wbg[(size_t)256 * 256];                      // gates weights
__device__ float g_gbias[256];
__device__ float g_psum [BATCH][6];                              // per-tile partial sums
__device__ float g_psum2[BATCH][6];
__device__ float g_scale[3][1792];
__device__ int   g_len  [3][1792];
__device__ int   g_src  [3][BATCH][TLEN];
__device__ float g_lam  [3][BATCH][TLEN];

// ---------------- cp.async helpers ----------------
#define CP16(dst, src) \
    asm volatile("cp.async.cg.shared.global [%0], [%1], 16;" :: "r"(dst), "l"(src))
#define CPCOMMIT() asm volatile("cp.async.commit_group;")
#define CPWAIT1()  asm volatile("cp.async.wait_group 1;")
#define CPWAIT0()  asm volatile("cp.async.wait_group 0;")

__device__ __forceinline__ uint32_t smem_u32(const void* p) {
    uint32_t a;
    asm("{ .reg .u64 t; cvta.to.shared.u64 t, %1; cvt.u32.u64 %0, t; }" : "=r"(a) : "l"(p));
    return a;
}

// ---------------- threefry2x32 (bit-exact JAX PRNG) ----------------
__device__ __forceinline__ unsigned tf_rotl(unsigned v, int r) {
    return (v << r) | (v >> (32 - r));
}
__device__ __forceinline__ void threefry2x32(unsigned k0, unsigned k1,
                                             unsigned x0, unsigned x1,
                                             unsigned& o0, unsigned& o1) {
    unsigned ks2 = k0 ^ k1 ^ 0x1BD11BDAu;
    x0 += k0; x1 += k1;
#define TF_RND(r) { x0 += x1; x1 = tf_rotl(x1, r); x1 ^= x0; }
    TF_RND(13) TF_RND(15) TF_RND(26) TF_RND(6)
    x0 += k1;  x1 += ks2 + 1u;
    TF_RND(17) TF_RND(29) TF_RND(16) TF_RND(24)
    x0 += ks2; x1 += k0 + 2u;
    TF_RND(13) TF_RND(15) TF_RND(26) TF_RND(6)
    x0 += k0;  x1 += k1 + 3u;
    TF_RND(17) TF_RND(29) TF_RND(16) TF_RND(24)
    x0 += k1;  x1 += ks2 + 4u;
    TF_RND(13) TF_RND(15) TF_RND(26) TF_RND(6)
#undef TF_RND
    o0 = x0 + ks2;
    o1 = x1 + k0 + 5u;
}
__device__ __forceinline__ unsigned tf_bits32(unsigned ka, unsigned kb, unsigned i) {
    unsigned o0, o1;
    threefry2x32(ka, kb, 0u, i, o0, o1);
    return o0 ^ o1;
}

__global__ void rng_bits_kernel() {
    int id = blockIdx.x * blockDim.x + threadIdx.x;
    if (id >= 3 * 1792) return;
    int l = id / 1792, m = id % 1792;
    unsigned ka, kb;
    threefry2x32(0u, 42u, 0u, (unsigned)l, ka, kb);
    unsigned k1a, k1b, k2a, k2b;
    threefry2x32(ka, kb, 0u, 0u, k1a, k1b);
    threefry2x32(ka, kb, 0u, 1u, k2a, k2b);
    unsigned ub = tf_bits32(k1a, k1b, (unsigned)m);
    float u = __uint_as_float((ub >> 9) | 0x3f800000u) - 1.0f;
    g_scale[l][m] = fmaxf(0.5f, u + 0.5f);
    unsigned ha, hb_, la, lb_;
    threefry2x32(k2a, k2b, 0u, 0u, ha, hb_);
    threefry2x32(k2a, k2b, 0u, 1u, la, lb_);
    unsigned hbits = tf_bits32(ha, hb_, (unsigned)m);
    unsigned lbits = tf_bits32(la, lb_, (unsigned)m);
    unsigned off = ((hbits % 13u) * 9u + (lbits % 13u)) % 13u;
    g_len[l][m] = 19 + (int)off;
}

__global__ void rng_scan_kernel() {
    int id = blockIdx.x * blockDim.x + threadIdx.x;
    if (id >= 3 * BATCH) return;
    int l = id / BATCH, b = id % BATCH;
    int cnt = 0, off = 0;
    for (int s = 0; s < 7; s++) {
        int m = b * 7 + s;
        float scale = g_scale[l][m];
        int   L     = g_len[l][m];
        float Lm1   = (float)(L - 1);
        float offf  = (float)off;
        for (int j = 0; j < 64; j++) {
            float is = (float)j / scale;
            float fl = floorf(is);
            if (fl < Lm1 && (fl + offf) < 191.0f) {
                if (cnt < TLEN) {
                    g_src[l][b][cnt] = (int)(fl + offf);
                    g_lam[l][b][cnt] = is - fl;
                }
                cnt++;
            }
        }
        off += L;
    }
    for (int t = cnt; t < TLEN; t++) g_src[l][b][t] = -1;
}

// ---------------- prep_x (layer 0 only): fp32 (B,Csrc,192) -> fp16 (B,200,Cpad) ----------------
__global__ __launch_bounds__(256)
void prep_x_kernel(const float* __restrict__ src, int Csrc, int Cpad,
                   __half* __restrict__ dst) {
    __shared__ float s[32][65];
    int c0 = blockIdx.x * 32;
    int t0 = blockIdx.y * 64;
    int b  = blockIdx.z;
    int tid = threadIdx.x;
    for (int i = tid; i < 32 * 64; i += 256) {
        int ci = i >> 6, tt = i & 63;
        int tsrc = t0 + tt - 2;
        float v = 0.f;
        int c = c0 + ci;
        if (c < Csrc && tsrc >= 0 && tsrc < TLEN)
            v = src[((size_t)b * Csrc + c) * TLEN + tsrc];
        s[ci][tt] = v;
    }
    __syncthreads();
    for (int i = tid; i < 64 * 32; i += 256) {
        int tdl = i >> 5, cl = i & 31;
        int td = t0 + tdl;
        if (td < TPAD)
            dst[((size_t)b * TPAD + td) * Cpad + c0 + cl] = __float2half_rn(s[cl][tdl]);
    }
}

// ---------------- prep_w: fp32 (taps,Csrc,256) -> fp16 (taps,Cpad,256) ----------------
__global__ __launch_bounds__(256)
void prep_w_kernel(const float* __restrict__ w, __half* __restrict__ dst,
                   int taps, int Csrc, int Cpad) {
    int n = gridDim.x * blockDim.x;
    int total = taps * Cpad * 256;
    for (int i = blockIdx.x * blockDim.x + threadIdx.x; i < total; i += n) {
        int tap = i / (Cpad * 256);
        int rem = i % (Cpad * 256);
        int c = rem / 256, co = rem % 256;
        float v = (c < Csrc) ? w[((size_t)tap * Csrc + c) * 256 + co] : 0.f;
        dst[i] = __float2half_rn(v);
    }
}

// ---------------- prep_gw: gates weight (1,256,256) + bias ----------------
__global__ __launch_bounds__(256)
void prep_gw_kernel(const float* __restrict__ kf, const float* __restrict__ bf,
                    const float* __restrict__ kb, const float* __restrict__ bb) {
    int i = blockIdx.x * blockDim.x + threadIdx.x;
    if (i < 256 * 256) {
        int c = i / 256, nn = i % 256;
        float v = (nn < 128) ? kf[(size_t)c * 128 + nn] : kb[(size_t)c * 128 + (nn - 128)];
        g_wbg[i] = __float2half_rn(v);
        if (i < 256) g_gbias[i] = (i < 128) ? bf[i] : bb[i - 128];
    }
}

// ---------------- legacy-HMMA GEMM: 2 batch samples per CTA, W frags reused ----------------
#define A_SZ 5440

template <int TAPS>
__global__ __launch_bounds__(256)
void mma_kernel(const __half* __restrict__ Ax,
                const __half* __restrict__ Wgt,
                const float* __restrict__ bias, float* __restrict__ out,
                int Cpad, int tap_offset, int mode) {
    constexpr int W_SZ  = TAPS * 32 * 272;
    constexpr int BUFSZ = W_SZ + 2 * A_SZ;

    extern __shared__ char dsm[];
    const uint32_t sb = smem_u32(dsm);

    const int bn = blockIdx.x;      // n tile (128 wide)
    const int bm = blockIdx.y;      // m tile (64 wide)
    const int bz = blockIdx.z;      // batch pair
    const int bb0 = bz * 2;
    const int tid  = threadIdx.x;
    const int wid  = tid >> 5;
    const int lane = tid & 31;
    const int wm = wid >> 2;        // 0..1
    const int wn = wid & 3;         // 0..3
    const int t0 = bm * 64;
    const int n0 = bn * 128;

    float acc[2][2][4][4];          // [batch][mt][nt][frag]
#pragma unroll
    for (int p = 0; p < 2; p++)
#pragma unroll
        for (int i = 0; i < 2; i++)
#pragma unroll
            for (int j = 0; j < 4; j++)
#pragma unroll
                for (int k = 0; k < 4; k++) acc[p][i][j][k] = 0.f;

    const int kchunks = Cpad >> 5;
    const int rs = Cpad >> 3;               // uint4 per activation row

    auto stage = [&](int it) {
        uint32_t buf = sb + (uint32_t)(it & 1) * BUFSZ;
        int k0 = it * 32;
        for (int i = tid; i < TAPS * 512; i += 256) {
            int tp = i >> 9, r = (i >> 4) & 31, q = i & 15;
            const uint4* srcW = (const uint4*)(Wgt + ((size_t)tp * Cpad + k0 + r) * 256 + n0);
            CP16(buf + (uint32_t)((tp * 32 + r) * 272 + q * 16), srcW + q);
        }
        const uint4* srcA0 = (const uint4*)(Ax + ((size_t)bb0 * TPAD + t0) * Cpad + k0);
        const uint4* srcA1 = (const uint4*)(Ax + ((size_t)(bb0 + 1) * TPAD + t0) * Cpad + k0);
        for (int i = tid; i < 272; i += 256) {
            int r = i >> 2, q = i & 3;
            CP16(buf + W_SZ + (uint32_t)(r * 80 + q * 16), srcA0 + (size_t)r * rs + q);
        }
        for (int i = tid; i < 272; i += 256) {
            int r = i >> 2, q = i & 3;
            CP16(buf + W_SZ + A_SZ + (uint32_t)(r * 80 + q * 16), srcA1 + (size_t)r * rs + q);
        }
    };

    stage(0);
    CPCOMMIT();

    for (int it = 0; it < kchunks; it++) {
        if (it + 1 < kchunks) {
            stage(it + 1);
            CPCOMMIT();
            CPWAIT1();
        } else {
            CPWAIT0();
        }
        __syncthreads();

        uint32_t buf = sb + (uint32_t)(it & 1) * BUFSZ;

#pragma unroll
        for (int tp = 0; tp < TAPS; tp++) {
            int cshift = tap_offset + tp;
#pragma unroll
            for (int kstep = 0; kstep < 2; kstep++) {
                // W fragments: loaded once, reused for both batches
                unsigned bfr[4][2];
#pragma unroll
                for (int np = 0; np < 2; np++) {
                    int row = kstep * 16 + (lane & 15);
                    int col = wn * 32 + np * 16 + ((lane >= 16) ? 8 : 0);
                    uint32_t addr = buf + (uint32_t)((tp * 32 + row) * 272 + col * 2);
                    unsigned r0, r1, r2, r3;
                    asm volatile("ldmatrix.sync.aligned.m8n8.x4.trans.shared.b16 {%0,%1,%2,%3}, [%4];"
                                 : "=r"(r0), "=r"(r1), "=r"(r2), "=r"(r3)
                                 : "r"(addr));
                    bfr[np * 2 + 0][0] = r0; bfr[np * 2 + 0][1] = r1;
                    bfr[np * 2 + 1][0] = r2; bfr[np * 2 + 1][1] = r3;
                }
#pragma unroll
                for (int p = 0; p < 2; p++) {
                    uint32_t sa = buf + W_SZ + (uint32_t)p * A_SZ;
                    unsigned ah[2][4];
#pragma unroll
                    for (int mt = 0; mt < 2; mt++) {
                        int row = wm * 32 + mt * 16 + cshift + (lane & 15);
                        int col = kstep * 16 + ((lane >> 4) * 8);
                        uint32_t adr = sa + (uint32_t)(row * 80 + col * 2);
                        asm volatile("ldmatrix.sync.aligned.m8n8.x4.shared.b16 {%0,%1,%2,%3}, [%4];"
                                     : "=r"(ah[mt][0]), "=r"(ah[mt][1]), "=r"(ah[mt][2]), "=r"(ah[mt][3])
                                     : "r"(adr));
                    }
#pragma unroll
                    for (int mt = 0; mt < 2; mt++)
#pragma unroll
                        for (int nt = 0; nt < 4; nt++) {
                            asm volatile(
                                "mma.sync.aligned.m16n8k16.row.col.f32.f16.f16.f32 "
                                "{%0,%1,%2,%3},{%4,%5,%6,%7},{%8,%9},{%0,%1,%2,%3};"
                                : "+f"(acc[p][mt][nt][0]), "+f"(acc[p][mt][nt][1]),
                                  "+f"(acc[p][mt][nt][2]), "+f"(acc[p][mt][nt][3])
                                : "r"(ah[mt][0]), "r"(ah[mt][1]), "r"(ah[mt][2]), "r"(ah[mt][3]),
                                  "r"(bfr[nt][0]), "r"(bfr[nt][1]));
                        }
                }
            }
        }
        __syncthreads();
    }

    // epilogue (+ fused partial GN stats in mode 0), per batch
    int gid = lane >> 2, tig = lane & 3;
    float psum[2] = {0.f, 0.f}, psum2[2] = {0.f, 0.f};
#pragma unroll
    for (int p = 0; p < 2; p++) {
        int bb = bb0 + p;
#pragma unroll
        for (int mt = 0; mt < 2; mt++) {
#pragma unroll
            for (int nt = 0; nt < 4; nt++) {
                int t  = t0 + wm * 32 + mt * 16 + gid;
                int co = n0 + wn * 32 + nt * 8 + tig * 2;
                float bv0 = bias[co], bv1 = bias[co + 1];
                float v0 = acc[p][mt][nt][0] + bv0;
                float v1 = acc[p][mt][nt][1] + bv1;
                float v2 = acc[p][mt][nt][2] + bv0;
                float v3 = acc[p][mt][nt][3] + bv1;
                if (mode == 0) {
                    float* yp0 = out + ((size_t)bb * 256 + co) * TLEN;
                    float* yp1 = yp0 + TLEN;
                    yp0[t]     = v0;
                    yp1[t]     = v1;
                    yp0[t + 8] = v2;
                    yp1[t + 8] = v3;
                    psum[p]  += v0 + v1 + v2 + v3;
                    psum2[p] = fmaf(v0, v0, fmaf(v1, v1, fmaf(v2, v2, fmaf(v3, v3, psum2[p]))));
                } else {
                    // gate-interleaved pre layout: col (g&31)*4 + (g>>5)
                    int dir0 = co >> 7, g0 = co & 127;
                    int dir1 = (co + 1) >> 7, g1 = (co + 1) & 127;
                    int c0i = (g0 & 31) * 4 + (g0 >> 5);
                    int c1i = (g1 & 31) * 4 + (g1 >> 5);
                    size_t r0 = ((size_t)(dir0 * BATCH + bb) * TLEN + t) * NGATE + c0i;
                    size_t r1 = ((size_t)(dir1 * BATCH + bb) * TLEN + t) * NGATE + c1i;
                    out[r0] = v0;
                    out[r1] = v1;
                    size_t r2 = ((size_t)(dir0 * BATCH + bb) * TLEN + t + 8) * NGATE + c0i;
                    size_t r3 = ((size_t)(dir1 * BATCH + bb) * TLEN + t + 8) * NGATE + c1i;
                    out[r2] = v2;
                    out[r3] = v3;
                }
            }
        }
    }
    if (mode == 0) {
        float* red = (float*)dsm;      // reuse staging smem (all loads done)
#pragma unroll
        for (int p = 0; p < 2; p++) {
            __syncthreads();
            red[tid] = psum[p];
            red[256 + tid] = psum2[p];
            __syncthreads();
            for (int k = 128; k > 0; k >>= 1) {
                if (tid < k) {
                    red[tid] += red[tid + k];
                    red[256 + tid] += red[256 + tid + k];
                }
                __syncthreads();
            }
            if (tid == 0) {
                g_psum [bb0 + p][bm * 2 + bn] = red[0];
                g_psum2[bb0 + p][bm * 2 + bn] = red[256];
            }
        }
    }
}

// ---------------- fused GN + ReLU + interp gather + fp16 transpose ----------------
__global__ __launch_bounds__(256)
void gather_fuse_kernel(const float* __restrict__ y,
                        __half* __restrict__ dst,
                        const float* __restrict__ gamma, const float* __restrict__ beta,
                        int layer) {
    __shared__ float s[TLEN][33];
    int b = blockIdx.x, cz = blockIdx.y;
    int c0 = cz * 32;
    int tid = threadIdx.x;

    float ts = 0.f, tq = 0.f;
#pragma unroll
    for (int i = 0; i < 6; i++) { ts += g_psum[b][i]; tq += g_psum2[b][i]; }
    const float inv_n = 1.0f / (float)(CENC * TLEN);
    float mean = ts * inv_n;
    float istd = rsqrtf(fmaxf(tq * inv_n - mean * mean, 0.f) + 1e-5f);

    for (int i = tid; i < 32 * TLEN; i += 256) {
        int ci = i / TLEN;
        int t = i % TLEN;
        int src = g_src[layer][b][t];
        float v = 0.f;
        if (src >= 0) {
            float lam = g_lam[layer][b][t];
            const float* yr = y + ((size_t)b * CENC + c0 + ci) * TLEN;
            float r0 = fmaxf((yr[src]     - mean) * istd * gamma[src]     + beta[src],     0.f);
            float r1 = fmaxf((yr[src + 1] - mean) * istd * gamma[src + 1] + beta[src + 1], 0.f);
            v = (1.f - lam) * r0 + lam * r1;
        }
        s[t][ci] = v;
    }
    __syncthreads();

    for (int i = tid; i < TLEN * 32; i += 256) {
        int t = i >> 5, ci = i & 31;
        dst[((size_t)b * TPAD + t + 2) * CENC + c0 + ci] = __float2half_rn(s[t][ci]);
    }
    if (tid < 256) {
        const int padrows[8] = {0, 1, 194, 195, 196, 197, 198, 199};
        int pr = padrows[tid >> 5], ci = tid & 31;
        dst[((size_t)b * TPAD + pr) * CENC + c0 + ci] = __float2half_rn(0.f);
    }
}

// ---------------- LSTM recurrence: float4 gate layout, 128-thread CTAs ----------------
__device__ __forceinline__ float sigm(float x) { return 1.f / (1.f + expf(-x)); }

__global__ __launch_bounds__(128)
void lstm_kernel(const float* __restrict__ pre,
                 const float* __restrict__ rf, const float* __restrict__ rb,
                 float* __restrict__ out) {
    __shared__ __align__(16) float4 Rs4[32][32];
    int dir = blockIdx.y;
    const float* R = dir ? rb : rf;
    for (int i = threadIdx.x; i < 32 * 32; i += 128) {
        int j = i >> 5, l = i & 31;
        Rs4[j][l] = make_float4(R[j * 128 + l],      R[j * 128 + 32 + l],
                                R[j * 128 + 64 + l], R[j * 128 + 96 + l]);
    }
    __syncthreads();

    int warp = threadIdx.x >> 5, lane = threadIdx.x & 31;
    int b = blockIdx.x * 4 + warp;
    float h = 0.f, c = 0.f;
    const float4* preb = (const float4*)(pre + (((size_t)dir * BATCH + b) * TLEN) * NGATE);

    for (int s = 0; s < TLEN; s++) {
        int t = dir ? (TLEN - 1 - s) : s;
        float4 z = preb[(size_t)t * 32 + lane];
#pragma unroll
        for (int j = 0; j < 32; j++) {
            float hj = __shfl_sync(0xffffffffu, h, j);
            float4 r = Rs4[j][lane];
            z.x = fmaf(hj, r.x, z.x);
            z.y = fmaf(hj, r.y, z.y);
            z.z = fmaf(hj, r.z, z.z);
            z.w = fmaf(hj, r.w, z.w);
        }
        c = sigm(z.y) * c + sigm(z.x) * tanhf(z.z);
        h = sigm(z.w) * tanhf(c);
        out[((size_t)b * TLEN + t) * 64 + dir * 32 + lane] = h;
    }
}

// ---------------- launch ----------------
extern "C" void kernel_launch(void* const* d_in, const int* in_sizes, int n_in,
                              void* d_out, int out_size) {
    const float* x   = (const float*)d_in[0];
    const float* w0  = (const float*)d_in[1];
    const float* b0  = (const float*)d_in[2];
    const float* w1  = (const float*)d_in[3];
    const float* b1  = (const float*)d_in[4];
    const float* w2  = (const float*)d_in[5];
    const float* b2  = (const float*)d_in[6];
    const float* g0  = (const float*)d_in[7];
    const float* be0 = (const float*)d_in[8];
    const float* g1  = (const float*)d_in[9];
    const float* be1 = (const float*)d_in[10];
    const float* g2  = (const float*)d_in[11];
    const float* be2 = (const float*)d_in[12];
    const float* kf  = (const float*)d_in[13];
    const float* rf  = (const float*)d_in[14];
    const float* bf  = (const float*)d_in[15];
    const float* kb  = (const float*)d_in[16];
    const float* rb  = (const float*)d_in[17];
    const float* bb  = (const float*)d_in[18];

    float *bufy, *pre, *gbias;
    __half *ax, *wb0, *wb1, *wb2, *wbg;
    cudaGetSymbolAddress((void**)&bufy, g_bufy);
    cudaGetSymbolAddress((void**)&pre,  g_pre);
    cudaGetSymbolAddress((void**)&gbias, g_gbias);
    cudaGetSymbolAddress((void**)&ax,  g_ax);
    cudaGetSymbolAddress((void**)&wb0, g_wb0);
    cudaGetSymbolAddress((void**)&wb1, g_wb1);
    cudaGetSymbolAddress((void**)&wb2, g_wb2);
    cudaGetSymbolAddress((void**)&wbg, g_wbg);

    const int SMEM5 = 2 * (5 * 32 * 272 + 2 * A_SZ);   // 108800
    const int SMEM1 = 2 * (1 * 32 * 272 + 2 * A_SZ);   // 39168
    cudaFuncSetAttribute(mma_kernel<5>, cudaFuncAttributeMaxDynamicSharedMemorySize, SMEM5);
    cudaFuncSetAttribute(mma_kernel<1>, cudaFuncAttributeMaxDynamicSharedMemorySize, SMEM1);

    // independent preprocessing — all up front
    rng_bits_kernel<<<21, 256>>>();
    rng_scan_kernel<<<3, 256>>>();
    prep_w_kernel<<<288, 256>>>(w0, wb0, 5, 257, 288);
    prep_w_kernel<<<256, 256>>>(w1, wb1, 5, 256, 256);
    prep_w_kernel<<<256, 256>>>(w2, wb2, 5, 256, 256);
    prep_gw_kernel<<<256, 256>>>(kf, bf, kb, bb);
    prep_x_kernel<<<dim3(9, 4, BATCH), 256>>>(x, 257, 288, ax);

    dim3 gmma(2, 3, BATCH / 2);
    dim3 ggath(BATCH, 8);

    // layer 0 (Cpad=288)
    mma_kernel<5><<<gmma, 256, SMEM5>>>(ax, wb0, b0, bufy, 288, 0, 0);
    gather_fuse_kernel<<<ggath, 256>>>(bufy, ax, g0, be0, 0);
    // layer 1 (Cpad=256)
    mma_kernel<5><<<gmma, 256, SMEM5>>>(ax, wb1, b1, bufy, 256, 0, 0);
    gather_fuse_kernel<<<ggath, 256>>>(bufy, ax, g1, be1, 1);
    // layer 2
    mma_kernel<5><<<gmma, 256, SMEM5>>>(ax, wb2, b2, bufy, 256, 0, 0);
    gather_fuse_kernel<<<ggath, 256>>>(bufy, ax, g2, be2, 2);

    // gates GEMM: taps=1 at offset 2 (time t), mode 1 (gate-interleaved)
    mma_kernel<1><<<gmma, 256, SMEM1>>>(ax, wbg, gbias, pre, 256, 2, 1);

    lstm_kernel<<<dim3(64, 2), 128>>>(pre, rf, rb, (float*)d_out);
}

// round 15
// speedup vs baseline: 1.5926x; 1.0895x over previous
#include <cuda_runtime.h>
#include <cuda_fp16.h>
#include <math.h>
#include <stdint.h>

#define BATCH 256
#define TLEN  192
#define CENC  256
#define NGATE 128
#define NECK  32
#define TPAD  200
#define CPAD0 288

// ---------------- scratch ----------------
__device__ float g_bufy[(size_t)BATCH * CENC * TLEN];            // conv output (B,C,T)
__device__ float g_pre [(size_t)2 * BATCH * TLEN * NGATE];       // lstm pre-gates (gate-interleaved)
__device__ __half g_ax[(size_t)BATCH * TPAD * CPAD0];            // fp16 activations
__device__ __half g_wb0[(size_t)5 * 288 * 256];                  // layer0 weights (tap,c,co)
__device__ __half g_wb1[(size_t)5 * 256 * 256];
__device__ __half g_wb2[(size_t)5 * 256 * 256];
__device__ __half g_wbg[(size_t)256 * 256];                      // gates weights
__device__ float g_gbias[256];
__device__ float g_psum [BATCH][6];                              // per-tile partial sums
__device__ float g_psum2[BATCH][6];
__device__ float g_scale[3][1792];
__device__ int   g_len  [3][1792];
__device__ int   g_src  [3][BATCH][TLEN];
__device__ float g_lam  [3][BATCH][TLEN];

// ---------------- cp.async helpers ----------------
#define CP16(dst, src) \
    asm volatile("cp.async.cg.shared.global [%0], [%1], 16;" :: "r"(dst), "l"(src))
#define CPCOMMIT() asm volatile("cp.async.commit_group;")
#define CPWAIT1()  asm volatile("cp.async.wait_group 1;")
#define CPWAIT0()  asm volatile("cp.async.wait_group 0;")

__device__ __forceinline__ uint32_t smem_u32(const void* p) {
    uint32_t a;
    asm("{ .reg .u64 t; cvta.to.shared.u64 t, %1; cvt.u32.u64 %0, t; }" : "=r"(a) : "l"(p));
    return a;
}

// ---------------- threefry2x32 (bit-exact JAX PRNG) ----------------
__device__ __forceinline__ unsigned tf_rotl(unsigned v, int r) {
    return (v << r) | (v >> (32 - r));
}
__device__ __forceinline__ void threefry2x32(unsigned k0, unsigned k1,
                                             unsigned x0, unsigned x1,
                                             unsigned& o0, unsigned& o1) {
    unsigned ks2 = k0 ^ k1 ^ 0x1BD11BDAu;
    x0 += k0; x1 += k1;
#define TF_RND(r) { x0 += x1; x1 = tf_rotl(x1, r); x1 ^= x0; }
    TF_RND(13) TF_RND(15) TF_RND(26) TF_RND(6)
    x0 += k1;  x1 += ks2 + 1u;
    TF_RND(17) TF_RND(29) TF_RND(16) TF_RND(24)
    x0 += ks2; x1 += k0 + 2u;
    TF_RND(13) TF_RND(15) TF_RND(26) TF_RND(6)
    x0 += k0;  x1 += k1 + 3u;
    TF_RND(17) TF_RND(29) TF_RND(16) TF_RND(24)
    x0 += k1;  x1 += ks2 + 4u;
    TF_RND(13) TF_RND(15) TF_RND(26) TF_RND(6)
#undef TF_RND
    o0 = x0 + ks2;
    o1 = x1 + k0 + 5u;
}
__device__ __forceinline__ unsigned tf_bits32(unsigned ka, unsigned kb, unsigned i) {
    unsigned o0, o1;
    threefry2x32(ka, kb, 0u, i, o0, o1);
    return o0 ^ o1;
}

// ---------------- fused preprocessing: x-transpose + 3 conv weights + gates + rng_bits ----------------
// block ranges: [0,2304) x | [2304,2592) w0 | [2592,2848) w1 | [2848,3104) w2
//               [3104,3360) gw | [3360,3381) rng_bits
__global__ __launch_bounds__(256)
void prep_all_kernel(const float* __restrict__ x,
                     const float* __restrict__ w0, const float* __restrict__ w1,
                     const float* __restrict__ w2,
                     const float* __restrict__ kf, const float* __restrict__ bf,
                     const float* __restrict__ kb, const float* __restrict__ bb) {
    const int bid = blockIdx.x;
    const int tid = threadIdx.x;

    if (bid < 2304) {
        // activation transpose: batch b, channel tile c0..c0+31 -> g_ax (fp16, Cpad 288, t at +2)
        __shared__ float s[32][193];
        int b  = bid / 9;
        int c0 = (bid % 9) * 32;
        for (int i = tid; i < 32 * 192; i += 256) {
            int ci = i / 192, t = i % 192;
            int c = c0 + ci;
            s[ci][t] = (c < 257) ? x[((size_t)b * 257 + c) * TLEN + t] : 0.f;
        }
        __syncthreads();
        for (int i = tid; i < TPAD * 32; i += 256) {
            int td = i >> 5, ci = i & 31;
            int ts = td - 2;
            float v = (ts >= 0 && ts < TLEN) ? s[ci][ts] : 0.f;
            g_ax[((size_t)b * TPAD + td) * CPAD0 + c0 + ci] = __float2half_rn(v);
        }
    } else if (bid < 2592) {
        // w0: (5,257,256) -> (5,288,256)
        int lb = bid - 2304;
        const int total = 5 * 288 * 256;
        for (int i = lb * 256 + tid; i < total; i += 288 * 256) {
            int tap = i / (288 * 256);
            int rem = i % (288 * 256);
            int c = rem / 256, co = rem % 256;
            float v = (c < 257) ? w0[((size_t)tap * 257 + c) * 256 + co] : 0.f;
            g_wb0[i] = __float2half_rn(v);
        }
    } else if (bid < 2848) {
        int lb = bid - 2592;
        const int total = 5 * 256 * 256;
        for (int i = lb * 256 + tid; i < total; i += 256 * 256) {
            g_wb1[i] = __float2half_rn(w1[i]);
        }
    } else if (bid < 3104) {
        int lb = bid - 2848;
        const int total = 5 * 256 * 256;
        for (int i = lb * 256 + tid; i < total; i += 256 * 256) {
            g_wb2[i] = __float2half_rn(w2[i]);
        }
    } else if (bid < 3360) {
        int lb = bid - 3104;
        int i = lb * 256 + tid;           // exactly 65536 elems
        int c = i / 256, nn = i % 256;
        float v = (nn < 128) ? kf[(size_t)c * 128 + nn] : kb[(size_t)c * 128 + (nn - 128)];
        g_wbg[i] = __float2half_rn(v);
        if (i < 256) g_gbias[i] = (i < 128) ? bf[i] : bb[i - 128];
    } else {
        // rng_bits
        int id = (bid - 3360) * 256 + tid;
        if (id >= 3 * 1792) return;
        int l = id / 1792, m = id % 1792;
        unsigned ka, kb_;
        threefry2x32(0u, 42u, 0u, (unsigned)l, ka, kb_);
        unsigned k1a, k1b, k2a, k2b;
        threefry2x32(ka, kb_, 0u, 0u, k1a, k1b);
        threefry2x32(ka, kb_, 0u, 1u, k2a, k2b);
        unsigned ub = tf_bits32(k1a, k1b, (unsigned)m);
        float u = __uint_as_float((ub >> 9) | 0x3f800000u) - 1.0f;
        g_scale[l][m] = fmaxf(0.5f, u + 0.5f);
        unsigned ha, hb_, la, lb_;
        threefry2x32(k2a, k2b, 0u, 0u, ha, hb_);
        threefry2x32(k2a, k2b, 0u, 1u, la, lb_);
        unsigned hbits = tf_bits32(ha, hb_, (unsigned)m);
        unsigned lbits = tf_bits32(la, lb_, (unsigned)m);
        unsigned off = ((hbits % 13u) * 9u + (lbits % 13u)) % 13u;
        g_len[l][m] = 19 + (int)off;
    }
}

__global__ void rng_scan_kernel() {
    int id = blockIdx.x * blockDim.x + threadIdx.x;
    if (id >= 3 * BATCH) return;
    int l = id / BATCH, b = id % BATCH;
    int cnt = 0, off = 0;
    for (int s = 0; s < 7; s++) {
        int m = b * 7 + s;
        float scale = g_scale[l][m];
        int   L     = g_len[l][m];
        float Lm1   = (float)(L - 1);
        float offf  = (float)off;
        for (int j = 0; j < 64; j++) {
            float is = (float)j / scale;
            float fl = floorf(is);
            if (fl < Lm1 && (fl + offf) < 191.0f) {
                if (cnt < TLEN) {
                    g_src[l][b][cnt] = (int)(fl + offf);
                    g_lam[l][b][cnt] = is - fl;
                }
                cnt++;
            }
        }
        off += L;
    }
    for (int t = cnt; t < TLEN; t++) g_src[l][b][t] = -1;
}

// ---------------- legacy-HMMA GEMM: 2 batch samples per CTA, W frags reused ----------------
#define A_SZ 5440

template <int TAPS>
__global__ __launch_bounds__(256)
void mma_kernel(const __half* __restrict__ Ax,
                const __half* __restrict__ Wgt,
                const float* __restrict__ bias, float* __restrict__ out,
                int Cpad, int tap_offset, int mode) {
    constexpr int W_SZ  = TAPS * 32 * 272;
    constexpr int BUFSZ = W_SZ + 2 * A_SZ;

    extern __shared__ char dsm[];
    const uint32_t sb = smem_u32(dsm);

    const int bn = blockIdx.x;      // n tile (128 wide)
    const int bm = blockIdx.y;      // m tile (64 wide)
    const int bz = blockIdx.z;      // batch pair
    const int bb0 = bz * 2;
    const int tid  = threadIdx.x;
    const int wid  = tid >> 5;
    const int lane = tid & 31;
    const int wm = wid >> 2;        // 0..1
    const int wn = wid & 3;         // 0..3
    const int t0 = bm * 64;
    const int n0 = bn * 128;

    float acc[2][2][4][4];          // [batch][mt][nt][frag]
#pragma unroll
    for (int p = 0; p < 2; p++)
#pragma unroll
        for (int i = 0; i < 2; i++)
#pragma unroll
            for (int j = 0; j < 4; j++)
#pragma unroll
                for (int k = 0; k < 4; k++) acc[p][i][j][k] = 0.f;

    const int kchunks = Cpad >> 5;
    const int rs = Cpad >> 3;               // uint4 per activation row

    auto stage = [&](int it) {
        uint32_t buf = sb + (uint32_t)(it & 1) * BUFSZ;
        int k0 = it * 32;
        for (int i = tid; i < TAPS * 512; i += 256) {
            int tp = i >> 9, r = (i >> 4) & 31, q = i & 15;
            const uint4* srcW = (const uint4*)(Wgt + ((size_t)tp * Cpad + k0 + r) * 256 + n0);
            CP16(buf + (uint32_t)((tp * 32 + r) * 272 + q * 16), srcW + q);
        }
        const uint4* srcA0 = (const uint4*)(Ax + ((size_t)bb0 * TPAD + t0) * Cpad + k0);
        const uint4* srcA1 = (const uint4*)(Ax + ((size_t)(bb0 + 1) * TPAD + t0) * Cpad + k0);
        for (int i = tid; i < 272; i += 256) {
            int r = i >> 2, q = i & 3;
            CP16(buf + W_SZ + (uint32_t)(r * 80 + q * 16), srcA0 + (size_t)r * rs + q);
        }
        for (int i = tid; i < 272; i += 256) {
            int r = i >> 2, q = i & 3;
            CP16(buf + W_SZ + A_SZ + (uint32_t)(r * 80 + q * 16), srcA1 + (size_t)r * rs + q);
        }
    };

    stage(0);
    CPCOMMIT();

    for (int it = 0; it < kchunks; it++) {
        if (it + 1 < kchunks) {
            stage(it + 1);
            CPCOMMIT();
            CPWAIT1();
        } else {
            CPWAIT0();
        }
        __syncthreads();

        uint32_t buf = sb + (uint32_t)(it & 1) * BUFSZ;

#pragma unroll
        for (int tp = 0; tp < TAPS; tp++) {
            int cshift = tap_offset + tp;
#pragma unroll
            for (int kstep = 0; kstep < 2; kstep++) {
                // W fragments: loaded once, reused for both batches
                unsigned bfr[4][2];
#pragma unroll
                for (int np = 0; np < 2; np++) {
                    int row = kstep * 16 + (lane & 15);
                    int col = wn * 32 + np * 16 + ((lane >= 16) ? 8 : 0);
                    uint32_t addr = buf + (uint32_t)((tp * 32 + row) * 272 + col * 2);
                    unsigned r0, r1, r2, r3;
                    asm volatile("ldmatrix.sync.aligned.m8n8.x4.trans.shared.b16 {%0,%1,%2,%3}, [%4];"
                                 : "=r"(r0), "=r"(r1), "=r"(r2), "=r"(r3)
                                 : "r"(addr));
                    bfr[np * 2 + 0][0] = r0; bfr[np * 2 + 0][1] = r1;
                    bfr[np * 2 + 1][0] = r2; bfr[np * 2 + 1][1] = r3;
                }
#pragma unroll
                for (int p = 0; p < 2; p++) {
                    uint32_t sa = buf + W_SZ + (uint32_t)p * A_SZ;
                    unsigned ah[2][4];
#pragma unroll
                    for (int mt = 0; mt < 2; mt++) {
                        int row = wm * 32 + mt * 16 + cshift + (lane & 15);
                        int col = kstep * 16 + ((lane >> 4) * 8);
                        uint32_t adr = sa + (uint32_t)(row * 80 + col * 2);
                        asm volatile("ldmatrix.sync.aligned.m8n8.x4.shared.b16 {%0,%1,%2,%3}, [%4];"
                                     : "=r"(ah[mt][0]), "=r"(ah[mt][1]), "=r"(ah[mt][2]), "=r"(ah[mt][3])
                                     : "r"(adr));
                    }
#pragma unroll
                    for (int mt = 0; mt < 2; mt++)
#pragma unroll
                        for (int nt = 0; nt < 4; nt++) {
                            asm volatile(
                                "mma.sync.aligned.m16n8k16.row.col.f32.f16.f16.f32 "
                                "{%0,%1,%2,%3},{%4,%5,%6,%7},{%8,%9},{%0,%1,%2,%3};"
                                : "+f"(acc[p][mt][nt][0]), "+f"(acc[p][mt][nt][1]),
                                  "+f"(acc[p][mt][nt][2]), "+f"(acc[p][mt][nt][3])
                                : "r"(ah[mt][0]), "r"(ah[mt][1]), "r"(ah[mt][2]), "r"(ah[mt][3]),
                                  "r"(bfr[nt][0]), "r"(bfr[nt][1]));
                        }
                }
            }
        }
        __syncthreads();
    }

    // epilogue (+ fused partial GN stats in mode 0), per batch
    int gid = lane >> 2, tig = lane & 3;
    float psum[2] = {0.f, 0.f}, psum2[2] = {0.f, 0.f};
#pragma unroll
    for (int p = 0; p < 2; p++) {
        int bb = bb0 + p;
#pragma unroll
        for (int mt = 0; mt < 2; mt++) {
#pragma unroll
            for (int nt = 0; nt < 4; nt++) {
                int t  = t0 + wm * 32 + mt * 16 + gid;
                int co = n0 + wn * 32 + nt * 8 + tig * 2;
                float bv0 = bias[co], bv1 = bias[co + 1];
                float v0 = acc[p][mt][nt][0] + bv0;
                float v1 = acc[p][mt][nt][1] + bv1;
                float v2 = acc[p][mt][nt][2] + bv0;
                float v3 = acc[p][mt][nt][3] + bv1;
                if (mode == 0) {
                    float* yp0 = out + ((size_t)bb * 256 + co) * TLEN;
                    float* yp1 = yp0 + TLEN;
                    yp0[t]     = v0;
                    yp1[t]     = v1;
                    yp0[t + 8] = v2;
                    yp1[t + 8] = v3;
                    psum[p]  += v0 + v1 + v2 + v3;
                    psum2[p] = fmaf(v0, v0, fmaf(v1, v1, fmaf(v2, v2, fmaf(v3, v3, psum2[p]))));
                } else {
                    // gate-interleaved pre layout: col (g&31)*4 + (g>>5)
                    int dir0 = co >> 7, g0 = co & 127;
                    int dir1 = (co + 1) >> 7, g1 = (co + 1) & 127;
                    int c0i = (g0 & 31) * 4 + (g0 >> 5);
                    int c1i = (g1 & 31) * 4 + (g1 >> 5);
                    size_t r0 = ((size_t)(dir0 * BATCH + bb) * TLEN + t) * NGATE + c0i;
                    size_t r1 = ((size_t)(dir1 * BATCH + bb) * TLEN + t) * NGATE + c1i;
                    out[r0] = v0;
                    out[r1] = v1;
                    size_t r2 = ((size_t)(dir0 * BATCH + bb) * TLEN + t + 8) * NGATE + c0i;
                    size_t r3 = ((size_t)(dir1 * BATCH + bb) * TLEN + t + 8) * NGATE + c1i;
                    out[r2] = v2;
                    out[r3] = v3;
                }
            }
        }
    }
    if (mode == 0) {
        float* red = (float*)dsm;      // reuse staging smem (all loads done)
#pragma unroll
        for (int p = 0; p < 2; p++) {
            __syncthreads();
            red[tid] = psum[p];
            red[256 + tid] = psum2[p];
            __syncthreads();
            for (int k = 128; k > 0; k >>= 1) {
                if (tid < k) {
                    red[tid] += red[tid + k];
                    red[256 + tid] += red[256 + tid + k];
                }
                __syncthreads();
            }
            if (tid == 0) {
                g_psum [bb0 + p][bm * 2 + bn] = red[0];
                g_psum2[bb0 + p][bm * 2 + bn] = red[256];
            }
        }
    }
}

// ---------------- fused GN + ReLU + interp gather + fp16 transpose ----------------
__global__ __launch_bounds__(256)
void gather_fuse_kernel(const float* __restrict__ y,
                        __half* __restrict__ dst,
                        const float* __restrict__ gamma, const float* __restrict__ beta,
                        int layer) {
    __shared__ float s[TLEN][33];
    int b = blockIdx.x, cz = blockIdx.y;
    int c0 = cz * 32;
    int tid = threadIdx.x;

    float ts = 0.f, tq = 0.f;
#pragma unroll
    for (int i = 0; i < 6; i++) { ts += g_psum[b][i]; tq += g_psum2[b][i]; }
    const float inv_n = 1.0f / (float)(CENC * TLEN);
    float mean = ts * inv_n;
    float istd = rsqrtf(fmaxf(tq * inv_n - mean * mean, 0.f) + 1e-5f);

    for (int i = tid; i < 32 * TLEN; i += 256) {
        int ci = i / TLEN;
        int t = i % TLEN;
        int src = g_src[layer][b][t];
        float v = 0.f;
        if (src >= 0) {
            float lam = g_lam[layer][b][t];
            const float* yr = y + ((size_t)b * CENC + c0 + ci) * TLEN;
            float r0 = fmaxf((yr[src]     - mean) * istd * gamma[src]     + beta[src],     0.f);
            float r1 = fmaxf((yr[src + 1] - mean) * istd * gamma[src + 1] + beta[src + 1], 0.f);
            v = (1.f - lam) * r0 + lam * r1;
        }
        s[t][ci] = v;
    }
    __syncthreads();

    for (int i = tid; i < TLEN * 32; i += 256) {
        int t = i >> 5, ci = i & 31;
        dst[((size_t)b * TPAD + t + 2) * CENC + c0 + ci] = __float2half_rn(s[t][ci]);
    }
    if (tid < 256) {
        const int padrows[8] = {0, 1, 194, 195, 196, 197, 198, 199};
        int pr = padrows[tid >> 5], ci = tid & 31;
        dst[((size_t)b * TPAD + pr) * CENC + c0 + ci] = __float2half_rn(0.f);
    }
}

// ---------------- LSTM recurrence: float4 gate layout, fast-math activations ----------------
__device__ __forceinline__ float sigm(float x) {
    return __fdividef(1.f, 1.f + __expf(-x));
}
__device__ __forceinline__ float ftanh(float x) {
    return __fdividef(2.f, 1.f + __expf(-2.f * x)) - 1.f;
}

__global__ __launch_bounds__(128)
void lstm_kernel(const float* __restrict__ pre,
                 const float* __restrict__ rf, const float* __restrict__ rb,
                 float* __restrict__ out) {
    __shared__ __align__(16) float4 Rs4[32][32];
    int dir = blockIdx.y;
    const float* R = dir ? rb : rf;
    for (int i = threadIdx.x; i < 32 * 32; i += 128) {
        int j = i >> 5, l = i & 31;
        Rs4[j][l] = make_float4(R[j * 128 + l],      R[j * 128 + 32 + l],
                                R[j * 128 + 64 + l], R[j * 128 + 96 + l]);
    }
    __syncthreads();

    int warp = threadIdx.x >> 5, lane = threadIdx.x & 31;
    int b = blockIdx.x * 4 + warp;
    float h = 0.f, c = 0.f;
    const float4* preb = (const float4*)(pre + (((size_t)dir * BATCH + b) * TLEN) * NGATE);

    for (int s = 0; s < TLEN; s++) {
        int t = dir ? (TLEN - 1 - s) : s;
        float4 z = preb[(size_t)t * 32 + lane];
#pragma unroll
        for (int j = 0; j < 32; j++) {
            float hj = __shfl_sync(0xffffffffu, h, j);
            float4 r = Rs4[j][lane];
            z.x = fmaf(hj, r.x, z.x);
            z.y = fmaf(hj, r.y, z.y);
            z.z = fmaf(hj, r.z, z.z);
            z.w = fmaf(hj, r.w, z.w);
        }
        c = sigm(z.y) * c + sigm(z.x) * ftanh(z.z);
        h = sigm(z.w) * ftanh(c);
        out[((size_t)b * TLEN + t) * 64 + dir * 32 + lane] = h;
    }
}

// ---------------- launch ----------------
extern "C" void kernel_launch(void* const* d_in, const int* in_sizes, int n_in,
                              void* d_out, int out_size) {
    const float* x   = (const float*)d_in[0];
    const float* w0  = (const float*)d_in[1];
    const float* b0  = (const float*)d_in[2];
    const float* w1  = (const float*)d_in[3];
    const float* b1  = (const float*)d_in[4];
    const float* w2  = (const float*)d_in[5];
    const float* b2  = (const float*)d_in[6];
    const float* g0  = (const float*)d_in[7];
    const float* be0 = (const float*)d_in[8];
    const float* g1  = (const float*)d_in[9];
    const float* be1 = (const float*)d_in[10];
    const float* g2  = (const float*)d_in[11];
    const float* be2 = (const float*)d_in[12];
    const float* kf  = (const float*)d_in[13];
    const float* rf  = (const float*)d_in[14];
    const float* bf  = (const float*)d_in[15];
    const float* kb  = (const float*)d_in[16];
    const float* rb  = (const float*)d_in[17];
    const float* bb  = (const float*)d_in[18];

    float *bufy, *pre, *gbias;
    __half *ax, *wb0, *wb1, *wb2, *wbg;
    cudaGetSymbolAddress((void**)&bufy, g_bufy);
    cudaGetSymbolAddress((void**)&pre,  g_pre);
    cudaGetSymbolAddress((void**)&gbias, g_gbias);
    cudaGetSymbolAddress((void**)&ax,  g_ax);
    cudaGetSymbolAddress((void**)&wb0, g_wb0);
    cudaGetSymbolAddress((void**)&wb1, g_wb1);
    cudaGetSymbolAddress((void**)&wb2, g_wb2);
    cudaGetSymbolAddress((void**)&wbg, g_wbg);

    const int SMEM5 = 2 * (5 * 32 * 272 + 2 * A_SZ);   // 108800
    const int SMEM1 = 2 * (1 * 32 * 272 + 2 * A_SZ);   // 39168
    cudaFuncSetAttribute(mma_kernel<5>, cudaFuncAttributeMaxDynamicSharedMemorySize, SMEM5);
    cudaFuncSetAttribute(mma_kernel<1>, cudaFuncAttributeMaxDynamicSharedMemorySize, SMEM1);

    // all independent preprocessing in ONE launch
    prep_all_kernel<<<3381, 256>>>(x, w0, w1, w2, kf, bf, kb, bb);
    rng_scan_kernel<<<3, 256>>>();

    dim3 gmma(2, 3, BATCH / 2);
    dim3 ggath(BATCH, 8);

    // layer 0 (Cpad=288)
    mma_kernel<5><<<gmma, 256, SMEM5>>>(ax, wb0, b0, bufy, 288, 0, 0);
    gather_fuse_kernel<<<ggath, 256>>>(bufy, ax, g0, be0, 0);
    // layer 1 (Cpad=256)
    mma_kernel<5><<<gmma, 256, SMEM5>>>(ax, wb1, b1, bufy, 256, 0, 0);
    gather_fuse_kernel<<<ggath, 256>>>(bufy, ax, g1, be1, 1);
    // layer 2
    mma_kernel<5><<<gmma, 256, SMEM5>>>(ax, wb2, b2, bufy, 256, 0, 0);
    gather_fuse_kernel<<<ggath, 256>>>(bufy, ax, g2, be2, 2);

    // gates GEMM: taps=1 at offset 2 (time t), mode 1 (gate-interleaved)
    mma_kernel<1><<<gmma, 256, SMEM1>>>(ax, wbg, gbias, pre, 256, 2, 1);

    lstm_kernel<<<dim3(64, 2), 128>>>(pre, rf, rb, (float*)d_out);
}

// round 17
// speedup vs baseline: 1.6739x; 1.0510x over previous
#include <cuda_runtime.h>
#include <cuda_fp16.h>
#include <math.h>
#include <stdint.h>

#define BATCH 256
#define TLEN  192
#define CENC  256
#define NGATE 128
#define NECK  32
#define TPAD  200
#define CPAD0 288

// ---------------- scratch ----------------
__device__ float g_bufy[(size_t)BATCH * TLEN * CENC];            // conv output (B,T,C)
__device__ float g_pre [(size_t)2 * BATCH * TLEN * NGATE];       // lstm pre-gates (gate-interleaved)
__device__ __half g_ax[(size_t)BATCH * TPAD * CPAD0];            // fp16 activations
__device__ __half g_wb0[(size_t)5 * 288 * 256];                  // layer0 weights (tap,c,co)
__device__ __half g_wb1[(size_t)5 * 256 * 256];
__device__ __half g_wb2[(size_t)5 * 256 * 256];
__device__ __half g_wbg[(size_t)256 * 256];                      // gates weights
__device__ float g_gbias[256];
__device__ float g_psum [BATCH][6];                              // per-tile partial sums
__device__ float g_psum2[BATCH][6];
__device__ float g_scale[3][1792];
__device__ int   g_len  [3][1792];
__device__ int   g_src  [3][BATCH][TLEN];
__device__ float g_lam  [3][BATCH][TLEN];

// ---------------- cp.async helpers ----------------
#define CP16(dst, src) \
    asm volatile("cp.async.cg.shared.global [%0], [%1], 16;" :: "r"(dst), "l"(src))
#define CPCOMMIT() asm volatile("cp.async.commit_group;")
#define CPWAIT1()  asm volatile("cp.async.wait_group 1;")
#define CPWAIT0()  asm volatile("cp.async.wait_group 0;")

__device__ __forceinline__ uint32_t smem_u32(const void* p) {
    uint32_t a;
    asm("{ .reg .u64 t; cvta.to.shared.u64 t, %1; cvt.u32.u64 %0, t; }" : "=r"(a) : "l"(p));
    return a;
}

// ---------------- threefry2x32 (bit-exact JAX PRNG) ----------------
__device__ __forceinline__ unsigned tf_rotl(unsigned v, int r) {
    return (v << r) | (v >> (32 - r));
}
__device__ __forceinline__ void threefry2x32(unsigned k0, unsigned k1,
                                             unsigned x0, unsigned x1,
                                             unsigned& o0, unsigned& o1) {
    unsigned ks2 = k0 ^ k1 ^ 0x1BD11BDAu;
    x0 += k0; x1 += k1;
#define TF_RND(r) { x0 += x1; x1 = tf_rotl(x1, r); x1 ^= x0; }
    TF_RND(13) TF_RND(15) TF_RND(26) TF_RND(6)
    x0 += k1;  x1 += ks2 + 1u;
    TF_RND(17) TF_RND(29) TF_RND(16) TF_RND(24)
    x0 += ks2; x1 += k0 + 2u;
    TF_RND(13) TF_RND(15) TF_RND(26) TF_RND(6)
    x0 += k0;  x1 += k1 + 3u;
    TF_RND(17) TF_RND(29) TF_RND(16) TF_RND(24)
    x0 += k1;  x1 += ks2 + 4u;
    TF_RND(13) TF_RND(15) TF_RND(26) TF_RND(6)
#undef TF_RND
    o0 = x0 + ks2;
    o1 = x1 + k0 + 5u;
}
__device__ __forceinline__ unsigned tf_bits32(unsigned ka, unsigned kb, unsigned i) {
    unsigned o0, o1;
    threefry2x32(ka, kb, 0u, i, o0, o1);
    return o0 ^ o1;
}

// ---------------- fused preprocessing: x-transpose + 3 conv weights + gates + rng_bits ----------------
__global__ __launch_bounds__(256)
void prep_all_kernel(const float* __restrict__ x,
                     const float* __restrict__ w0, const float* __restrict__ w1,
                     const float* __restrict__ w2,
                     const float* __restrict__ kf, const float* __restrict__ bf,
                     const float* __restrict__ kb, const float* __restrict__ bb) {
    const int bid = blockIdx.x;
    const int tid = threadIdx.x;

    if (bid < 2304) {
        __shared__ float s[32][193];
        int b  = bid / 9;
        int c0 = (bid % 9) * 32;
        for (int i = tid; i < 32 * 192; i += 256) {
            int ci = i / 192, t = i % 192;
            int c = c0 + ci;
            s[ci][t] = (c < 257) ? x[((size_t)b * 257 + c) * TLEN + t] : 0.f;
        }
        __syncthreads();
        for (int i = tid; i < TPAD * 32; i += 256) {
            int td = i >> 5, ci = i & 31;
            int ts = td - 2;
            float v = (ts >= 0 && ts < TLEN) ? s[ci][ts] : 0.f;
            g_ax[((size_t)b * TPAD + td) * CPAD0 + c0 + ci] = __float2half_rn(v);
        }
    } else if (bid < 2592) {
        int lb = bid - 2304;
        const int total = 5 * 288 * 256;
        for (int i = lb * 256 + tid; i < total; i += 288 * 256) {
            int tap = i / (288 * 256);
            int rem = i % (288 * 256);
            int c = rem / 256, co = rem % 256;
            float v = (c < 257) ? w0[((size_t)tap * 257 + c) * 256 + co] : 0.f;
            g_wb0[i] = __float2half_rn(v);
        }
    } else if (bid < 2848) {
        int lb = bid - 2592;
        const int total = 5 * 256 * 256;
        for (int i = lb * 256 + tid; i < total; i += 256 * 256) {
            g_wb1[i] = __float2half_rn(w1[i]);
        }
    } else if (bid < 3104) {
        int lb = bid - 2848;
        const int total = 5 * 256 * 256;
        for (int i = lb * 256 + tid; i < total; i += 256 * 256) {
            g_wb2[i] = __float2half_rn(w2[i]);
        }
    } else if (bid < 3360) {
        int lb = bid - 3104;
        int i = lb * 256 + tid;
        int c = i / 256, nn = i % 256;
        float v = (nn < 128) ? kf[(size_t)c * 128 + nn] : kb[(size_t)c * 128 + (nn - 128)];
        g_wbg[i] = __float2half_rn(v);
        if (i < 256) g_gbias[i] = (i < 128) ? bf[i] : bb[i - 128];
    } else {
        int id = (bid - 3360) * 256 + tid;
        if (id >= 3 * 1792) return;
        int l = id / 1792, m = id % 1792;
        unsigned ka, kb_;
        threefry2x32(0u, 42u, 0u, (unsigned)l, ka, kb_);
        unsigned k1a, k1b, k2a, k2b;
        threefry2x32(ka, kb_, 0u, 0u, k1a, k1b);
        threefry2x32(ka, kb_, 0u, 1u, k2a, k2b);
        unsigned ub = tf_bits32(k1a, k1b, (unsigned)m);
        float u = __uint_as_float((ub >> 9) | 0x3f800000u) - 1.0f;
        g_scale[l][m] = fmaxf(0.5f, u + 0.5f);
        unsigned ha, hb_, la, lb_;
        threefry2x32(k2a, k2b, 0u, 0u, ha, hb_);
        threefry2x32(k2a, k2b, 0u, 1u, la, lb_);
        unsigned hbits = tf_bits32(ha, hb_, (unsigned)m);
        unsigned lbits = tf_bits32(la, lb_, (unsigned)m);
        unsigned off = ((hbits % 13u) * 9u + (lbits % 13u)) % 13u;
        g_len[l][m] = 19 + (int)off;
    }
}

__global__ void rng_scan_kernel() {
    int id = blockIdx.x * blockDim.x + threadIdx.x;
    if (id >= 3 * BATCH) return;
    int l = id / BATCH, b = id % BATCH;
    int cnt = 0, off = 0;
    for (int s = 0; s < 7; s++) {
        int m = b * 7 + s;
        float scale = g_scale[l][m];
        int   L     = g_len[l][m];
        float Lm1   = (float)(L - 1);
        float offf  = (float)off;
        for (int j = 0; j < 64; j++) {
            float is = (float)j / scale;
            float fl = floorf(is);
            if (fl < Lm1 && (fl + offf) < 191.0f) {
                if (cnt < TLEN) {
                    g_src[l][b][cnt] = (int)(fl + offf);
                    g_lam[l][b][cnt] = is - fl;
                }
                cnt++;
            }
        }
        off += L;
    }
    for (int t = cnt; t < TLEN; t++) g_src[l][b][t] = -1;
}

// ---------------- legacy-HMMA GEMM: 2 batch samples per CTA, W frags reused ----------------
#define A_SZ 5440

template <int TAPS>
__global__ __launch_bounds__(256)
void mma_kernel(const __half* __restrict__ Ax,
                const __half* __restrict__ Wgt,
                const float* __restrict__ bias, float* __restrict__ out,
                int Cpad, int tap_offset, int mode) {
    constexpr int W_SZ  = TAPS * 32 * 272;
    constexpr int BUFSZ = W_SZ + 2 * A_SZ;

    extern __shared__ char dsm[];
    const uint32_t sb = smem_u32(dsm);

    const int bn = blockIdx.x;      // n tile (128 wide)
    const int bm = blockIdx.y;      // m tile (64 wide)
    const int bz = blockIdx.z;      // batch pair
    const int bb0 = bz * 2;
    const int tid  = threadIdx.x;
    const int wid  = tid >> 5;
    const int lane = tid & 31;
    const int wm = wid >> 2;        // 0..1
    const int wn = wid & 3;         // 0..3
    const int t0 = bm * 64;
    const int n0 = bn * 128;

    float acc[2][2][4][4];          // [batch][mt][nt][frag]
#pragma unroll
    for (int p = 0; p < 2; p++)
#pragma unroll
        for (int i = 0; i < 2; i++)
#pragma unroll
            for (int j = 0; j < 4; j++)
#pragma unroll
                for (int k = 0; k < 4; k++) acc[p][i][j][k] = 0.f;

    const int kchunks = Cpad >> 5;
    const int rs = Cpad >> 3;               // uint4 per activation row

    auto stage = [&](int it) {
        uint32_t buf = sb + (uint32_t)(it & 1) * BUFSZ;
        int k0 = it * 32;
        for (int i = tid; i < TAPS * 512; i += 256) {
            int tp = i >> 9, r = (i >> 4) & 31, q = i & 15;
            const uint4* srcW = (const uint4*)(Wgt + ((size_t)tp * Cpad + k0 + r) * 256 + n0);
            CP16(buf + (uint32_t)((tp * 32 + r) * 272 + q * 16), srcW + q);
        }
        const uint4* srcA0 = (const uint4*)(Ax + ((size_t)bb0 * TPAD + t0) * Cpad + k0);
        const uint4* srcA1 = (const uint4*)(Ax + ((size_t)(bb0 + 1) * TPAD + t0) * Cpad + k0);
        for (int i = tid; i < 272; i += 256) {
            int r = i >> 2, q = i & 3;
            CP16(buf + W_SZ + (uint32_t)(r * 80 + q * 16), srcA0 + (size_t)r * rs + q);
        }
        for (int i = tid; i < 272; i += 256) {
            int r = i >> 2, q = i & 3;
            CP16(buf + W_SZ + A_SZ + (uint32_t)(r * 80 + q * 16), srcA1 + (size_t)r * rs + q);
        }
    };

    stage(0);
    CPCOMMIT();

    for (int it = 0; it < kchunks; it++) {
        if (it + 1 < kchunks) {
            stage(it + 1);
            CPCOMMIT();
            CPWAIT1();
        } else {
            CPWAIT0();
        }
        __syncthreads();

        uint32_t buf = sb + (uint32_t)(it & 1) * BUFSZ;

#pragma unroll
        for (int tp = 0; tp < TAPS; tp++) {
            int cshift = tap_offset + tp;
#pragma unroll
            for (int kstep = 0; kstep < 2; kstep++) {
                unsigned bfr[4][2];
#pragma unroll
                for (int np = 0; np < 2; np++) {
                    int row = kstep * 16 + (lane & 15);
                    int col = wn * 32 + np * 16 + ((lane >= 16) ? 8 : 0);
                    uint32_t addr = buf + (uint32_t)((tp * 32 + row) * 272 + col * 2);
                    unsigned r0, r1, r2, r3;
                    asm volatile("ldmatrix.sync.aligned.m8n8.x4.trans.shared.b16 {%0,%1,%2,%3}, [%4];"
                                 : "=r"(r0), "=r"(r1), "=r"(r2), "=r"(r3)
                                 : "r"(addr));
                    bfr[np * 2 + 0][0] = r0; bfr[np * 2 + 0][1] = r1;
                    bfr[np * 2 + 1][0] = r2; bfr[np * 2 + 1][1] = r3;
                }
#pragma unroll
                for (int p = 0; p < 2; p++) {
                    uint32_t sa = buf + W_SZ + (uint32_t)p * A_SZ;
                    unsigned ah[2][4];
#pragma unroll
                    for (int mt = 0; mt < 2; mt++) {
                        int row = wm * 32 + mt * 16 + cshift + (lane & 15);
                        int col = kstep * 16 + ((lane >> 4) * 8);
                        uint32_t adr = sa + (uint32_t)(row * 80 + col * 2);
                        asm volatile("ldmatrix.sync.aligned.m8n8.x4.shared.b16 {%0,%1,%2,%3}, [%4];"
                                     : "=r"(ah[mt][0]), "=r"(ah[mt][1]), "=r"(ah[mt][2]), "=r"(ah[mt][3])
                                     : "r"(adr));
                    }
#pragma unroll
                    for (int mt = 0; mt < 2; mt++)
#pragma unroll
                        for (int nt = 0; nt < 4; nt++) {
                            asm volatile(
                                "mma.sync.aligned.m16n8k16.row.col.f32.f16.f16.f32 "
                                "{%0,%1,%2,%3},{%4,%5,%6,%7},{%8,%9},{%0,%1,%2,%3};"
                                : "+f"(acc[p][mt][nt][0]), "+f"(acc[p][mt][nt][1]),
                                  "+f"(acc[p][mt][nt][2]), "+f"(acc[p][mt][nt][3])
                                : "r"(ah[mt][0]), "r"(ah[mt][1]), "r"(ah[mt][2]), "r"(ah[mt][3]),
                                  "r"(bfr[nt][0]), "r"(bfr[nt][1]));
                        }
                }
            }
        }
        __syncthreads();
    }

    // epilogue (+ fused partial GN stats in mode 0), per batch
    int gid = lane >> 2, tig = lane & 3;
    float psum[2] = {0.f, 0.f}, psum2[2] = {0.f, 0.f};
#pragma unroll
    for (int p = 0; p < 2; p++) {
        int bb = bb0 + p;
#pragma unroll
        for (int mt = 0; mt < 2; mt++) {
#pragma unroll
            for (int nt = 0; nt < 4; nt++) {
                int t  = t0 + wm * 32 + mt * 16 + gid;
                int co = n0 + wn * 32 + nt * 8 + tig * 2;
                float bv0 = bias[co], bv1 = bias[co + 1];
                float v0 = acc[p][mt][nt][0] + bv0;
                float v1 = acc[p][mt][nt][1] + bv1;
                float v2 = acc[p][mt][nt][2] + bv0;
                float v3 = acc[p][mt][nt][3] + bv1;
                if (mode == 0) {
                    // y layout (B, T, C)
                    float* yp = out + ((size_t)bb * TLEN + t) * CENC + co;
                    yp[0] = v0;
                    yp[1] = v1;
                    yp[8 * CENC]     = v2;
                    yp[8 * CENC + 1] = v3;
                    psum[p]  += v0 + v1 + v2 + v3;
                    psum2[p] = fmaf(v0, v0, fmaf(v1, v1, fmaf(v2, v2, fmaf(v3, v3, psum2[p]))));
                } else {
                    // gate-interleaved pre layout: col (g&31)*4 + (g>>5)
                    int dir0 = co >> 7, g0 = co & 127;
                    int dir1 = (co + 1) >> 7, g1 = (co + 1) & 127;
                    int c0i = (g0 & 31) * 4 + (g0 >> 5);
                    int c1i = (g1 & 31) * 4 + (g1 >> 5);
                    size_t r0 = ((size_t)(dir0 * BATCH + bb) * TLEN + t) * NGATE + c0i;
                    size_t r1 = ((size_t)(dir1 * BATCH + bb) * TLEN + t) * NGATE + c1i;
                    out[r0] = v0;
                    out[r1] = v1;
                    size_t r2 = ((size_t)(dir0 * BATCH + bb) * TLEN + t + 8) * NGATE + c0i;
                    size_t r3 = ((size_t)(dir1 * BATCH + bb) * TLEN + t + 8) * NGATE + c1i;
                    out[r2] = v2;
                    out[r3] = v3;
                }
            }
        }
    }
    if (mode == 0) {
        float* red = (float*)dsm;      // reuse staging smem (all loads done)
#pragma unroll
        for (int p = 0; p < 2; p++) {
            __syncthreads();
            red[tid] = psum[p];
            red[256 + tid] = psum2[p];
            __syncthreads();
            for (int k = 128; k > 0; k >>= 1) {
                if (tid < k) {
                    red[tid] += red[tid + k];
                    red[256 + tid] += red[256 + tid + k];
                }
                __syncthreads();
            }
            if (tid == 0) {
                g_psum [bb0 + p][bm * 2 + bn] = red[0];
                g_psum2[bb0 + p][bm * 2 + bn] = red[256];
            }
        }
    }
}

// ---------------- fused GN + ReLU + interp gather (coalesced, y is (B,T,C)) ----------------
__global__ __launch_bounds__(256)
void gather_fuse_kernel(const float* __restrict__ y,
                        __half* __restrict__ dst,
                        const float* __restrict__ gamma, const float* __restrict__ beta,
                        int layer) {
    int b = blockIdx.x, tz = blockIdx.y;
    int c = threadIdx.x;

    float ts = 0.f, tq = 0.f;
#pragma unroll
    for (int i = 0; i < 6; i++) { ts += g_psum[b][i]; tq += g_psum2[b][i]; }
    const float inv_n = 1.0f / (float)(CENC * TLEN);
    float mean = ts * inv_n;
    float istd = rsqrtf(fmaxf(tq * inv_n - mean * mean, 0.f) + 1e-5f);

    const float* yb = y + (size_t)b * TLEN * CENC;
    __half* db = dst + (size_t)b * TPAD * CENC;

#pragma unroll 4
    for (int tt = 0; tt < 32; tt++) {
        int t = tz * 32 + tt;
        int src = g_src[layer][b][t];
        float v = 0.f;
        if (src >= 0) {
            float lam = g_lam[layer][b][t];
            float gm0 = gamma[src] * istd, bt0 = beta[src] - mean * gm0;
            float gm1 = gamma[src + 1] * istd, bt1 = beta[src + 1] - mean * gm1;
            const float* rp = yb + (size_t)src * CENC + c;
            float a0 = fmaxf(fmaf(rp[0], gm0, bt0), 0.f);
            float a1 = fmaxf(fmaf(rp[CENC], gm1, bt1), 0.f);
            v = (1.f - lam) * a0 + lam * a1;
        }
        db[(size_t)(t + 2) * CENC + c] = __float2half_rn(v);
    }
    // zero pad rows of the STRIDE-256 layout (rows 0,1 and 194..199)
    if (tz == 0) {
        db[c] = __float2half_rn(0.f);
        db[CENC + c] = __float2half_rn(0.f);
    } else if (tz == 5) {
#pragma unroll
        for (int pr = 194; pr < 200; pr++)
            db[(size_t)pr * CENC + c] = __float2half_rn(0.f);
    }
}

// ---------------- LSTM recurrence: float4 gate layout, fast-math activations ----------------
__device__ __forceinline__ float sigm(float x) {
    return __fdividef(1.f, 1.f + __expf(-x));
}
__device__ __forceinline__ float ftanh(float x) {
    return __fdividef(2.f, 1.f + __expf(-2.f * x)) - 1.f;
}

__global__ __launch_bounds__(128)
void lstm_kernel(const float* __restrict__ pre,
                 const float* __restrict__ rf, const float* __restrict__ rb,
                 float* __restrict__ out) {
    __shared__ __align__(16) float4 Rs4[32][32];
    int dir = blockIdx.y;
    const float* R = dir ? rb : rf;
    for (int i = threadIdx.x; i < 32 * 32; i += 128) {
        int j = i >> 5, l = i & 31;
        Rs4[j][l] = make_float4(R[j * 128 + l],      R[j * 128 + 32 + l],
                                R[j * 128 + 64 + l], R[j * 128 + 96 + l]);
    }
    __syncthreads();

    int warp = threadIdx.x >> 5, lane = threadIdx.x & 31;
    int b = blockIdx.x * 4 + warp;
    float h = 0.f, c = 0.f;
    const float4* preb = (const float4*)(pre + (((size_t)dir * BATCH + b) * TLEN) * NGATE);

    for (int s = 0; s < TLEN; s++) {
        int t = dir ? (TLEN - 1 - s) : s;
        float4 z = preb[(size_t)t * 32 + lane];
#pragma unroll
        for (int j = 0; j < 32; j++) {
            float hj = __shfl_sync(0xffffffffu, h, j);
            float4 r = Rs4[j][lane];
            z.x = fmaf(hj, r.x, z.x);
            z.y = fmaf(hj, r.y, z.y);
            z.z = fmaf(hj, r.z, z.z);
            z.w = fmaf(hj, r.w, z.w);
        }
        c = sigm(z.y) * c + sigm(z.x) * ftanh(z.z);
        h = sigm(z.w) * ftanh(c);
        out[((size_t)b * TLEN + t) * 64 + dir * 32 + lane] = h;
    }
}

// ---------------- launch ----------------
extern "C" void kernel_launch(void* const* d_in, const int* in_sizes, int n_in,
                              void* d_out, int out_size) {
    const float* x   = (const float*)d_in[0];
    const float* w0  = (const float*)d_in[1];
    const float* b0  = (const float*)d_in[2];
    const float* w1  = (const float*)d_in[3];
    const float* b1  = (const float*)d_in[4];
    const float* w2  = (const float*)d_in[5];
    const float* b2  = (const float*)d_in[6];
    const float* g0  = (const float*)d_in[7];
    const float* be0 = (const float*)d_in[8];
    const float* g1  = (const float*)d_in[9];
    const float* be1 = (const float*)d_in[10];
    const float* g2  = (const float*)d_in[11];
    const float* be2 = (const float*)d_in[12];
    const float* kf  = (const float*)d_in[13];
    const float* rf  = (const float*)d_in[14];
    const float* bf  = (const float*)d_in[15];
    const float* kb  = (const float*)d_in[16];
    const float* rb  = (const float*)d_in[17];
    const float* bb  = (const float*)d_in[18];

    float *bufy, *pre;
    __half *ax, *wb0, *wb1, *wb2, *wbg;
    float *gbias;
    cudaGetSymbolAddress((void**)&bufy, g_bufy);
    cudaGetSymbolAddress((void**)&pre,  g_pre);
    cudaGetSymbolAddress((void**)&gbias, g_gbias);
    cudaGetSymbolAddress((void**)&ax,  g_ax);
    cudaGetSymbolAddress((void**)&wb0, g_wb0);
    cudaGetSymbolAddress((void**)&wb1, g_wb1);
    cudaGetSymbolAddress((void**)&wb2, g_wb2);
    cudaGetSymbolAddress((void**)&wbg, g_wbg);

    const int SMEM5 = 2 * (5 * 32 * 272 + 2 * A_SZ);   // 108800
    const int SMEM1 = 2 * (1 * 32 * 272 + 2 * A_SZ);   // 39168
    cudaFuncSetAttribute(mma_kernel<5>, cudaFuncAttributeMaxDynamicSharedMemorySize, SMEM5);
    cudaFuncSetAttribute(mma_kernel<1>, cudaFuncAttributeMaxDynamicSharedMemorySize, SMEM1);

    // all independent preprocessing in ONE launch
    prep_all_kernel<<<3381, 256>>>(x, w0, w1, w2, kf, bf, kb, bb);
    rng_scan_kernel<<<3, 256>>>();

    dim3 gmma(2, 3, BATCH / 2);
    dim3 ggath(BATCH, 6);

    // layer 0 (Cpad=288)
    mma_kernel<5><<<gmma, 256, SMEM5>>>(ax, wb0, b0, bufy, 288, 0, 0);
    gather_fuse_kernel<<<ggath, 256>>>(bufy, ax, g0, be0, 0);
    // layer 1 (Cpad=256)
    mma_kernel<5><<<gmma, 256, SMEM5>>>(ax, wb1, b1, bufy, 256, 0, 0);
    gather_fuse_kernel<<<ggath, 256>>>(bufy, ax, g1, be1, 1);
    // layer 2
    mma_kernel<5><<<gmma, 256, SMEM5>>>(ax, wb2, b2, bufy, 256, 0, 0);
    gather_fuse_kernel<<<ggath, 256>>>(bufy, ax, g2, be2, 2);

    // gates GEMM: taps=1 at offset 2 (time t), mode 1 (gate-interleaved)
    mma_kernel<1><<<gmma, 256, SMEM1>>>(ax, wbg, gbias, pre, 256, 2, 1);

    lstm_kernel<<<dim3(64, 2), 128>>>(pre, rf, rb, (float*)d_out);
}